// round 1
// baseline (speedup 1.0000x reference)
#include <cuda_runtime.h>
#include <cuda_bf16.h>
#include <cstdint>
#include <math.h>

#define T_STEPS 512
#define BATCH   64
#define IN_DIM  1024
#define HID     1024
#define GATES   4096          // 4*HID
#define NCTA    128           // recurrent CTAs (<=148 SMs, 1 CTA/SM -> one wave)

// ---- scratch (static __device__ arrays: allocation-free per harness rules) ----
__device__ float g_xw[(size_t)T_STEPS * BATCH * GATES];   // 512 MB: x@W_x + b
__device__ int   g_flags[T_STEPS];                        // per-step arrival counters

// ---- helpers ----
__device__ __forceinline__ void split_f(float v, __nv_bfloat16& hi, __nv_bfloat16& lo) {
    hi = __float2bfloat16(v);
    lo = __float2bfloat16(v - __bfloat162float(hi));
}
__device__ __forceinline__ uint32_t pack2(__nv_bfloat16 a, __nv_bfloat16 b) {
    __nv_bfloat162 t = __halves2bfloat162(a, b);
    return *reinterpret_cast<uint32_t*>(&t);
}
__device__ __forceinline__ void mma16816(float* c, const uint32_t* a, const uint32_t* b) {
    asm volatile(
        "mma.sync.aligned.m16n8k16.row.col.f32.bf16.bf16.f32 "
        "{%0,%1,%2,%3}, {%4,%5,%6,%7}, {%8,%9}, {%0,%1,%2,%3};\n"
        : "+f"(c[0]), "+f"(c[1]), "+f"(c[2]), "+f"(c[3])
        : "r"(a[0]), "r"(a[1]), "r"(a[2]), "r"(a[3]), "r"(b[0]), "r"(b[1]));
}

// =====================================================================
// Phase A: xw[m,n] = x[m,:] @ W_x[:,n] + b[n]   (M=32768, N=4096, K=1024)
// split-bf16, 3 mma terms, CTA tile 128x128, BK=32, 256 threads
// =====================================================================
__global__ __launch_bounds__(256, 1)
void xw_gemm_kernel(const float* __restrict__ X,
                    const float* __restrict__ W,
                    const float* __restrict__ bias)
{
    __shared__ uint32_t As_hi[128][17];          // 128 x 32 bf16 (pairs), padded
    __shared__ uint32_t As_lo[128][17];
    __shared__ __nv_bfloat16 Bs_hi[128][34];     // [n][k], padded
    __shared__ __nv_bfloat16 Bs_lo[128][34];

    const int tid  = threadIdx.x;
    const int lane = tid & 31;
    const int warp = tid >> 5;
    const int g    = lane >> 2;
    const int tg   = lane & 3;
    const int wm   = (warp & 3) * 32;    // warp tile 32(m) x 64(n)
    const int wn   = (warp >> 2) * 64;
    const size_t m0 = (size_t)blockIdx.y * 128;
    const int    n0 = blockIdx.x * 128;

    // re-zero sync flags for the recurrent kernel every launch (replay-safe)
    if (blockIdx.x == 0 && blockIdx.y == 0) {
        g_flags[tid] = 0; g_flags[tid + 256] = 0;
    }

    float acc[2][8][4];
    #pragma unroll
    for (int i = 0; i < 2; i++)
        #pragma unroll
        for (int j = 0; j < 8; j++)
            #pragma unroll
            for (int k = 0; k < 4; k++) acc[i][j][k] = 0.f;

    for (int k0 = 0; k0 < IN_DIM; k0 += 32) {
        // ---- load A tile (x): 128 rows x 32 k, float4 per thread x4 ----
        #pragma unroll
        for (int i = 0; i < 4; i++) {
            int idx = tid + 256 * i;            // 0..1023 float4s
            int m   = idx >> 3;                 // 8 float4 per row
            int kq  = idx & 7;
            float4 v = *(const float4*)(X + (m0 + m) * IN_DIM + k0 + kq * 4);
            __nv_bfloat16 h0,h1,h2,h3,l0,l1,l2,l3;
            split_f(v.x,h0,l0); split_f(v.y,h1,l1);
            split_f(v.z,h2,l2); split_f(v.w,h3,l3);
            As_hi[m][kq*2]   = pack2(h0,h1);
            As_hi[m][kq*2+1] = pack2(h2,h3);
            As_lo[m][kq*2]   = pack2(l0,l1);
            As_lo[m][kq*2+1] = pack2(l2,l3);
        }
        // ---- load B tile (W_x): 32 k-rows x 128 n, transpose into [n][k] ----
        #pragma unroll
        for (int i = 0; i < 4; i++) {
            int idx = tid + 256 * i;            // 0..1023 float4s
            int kk  = idx >> 5;                 // 32 float4 per row
            int nq  = idx & 31;
            float4 v = *(const float4*)(W + (size_t)(k0 + kk) * GATES + n0 + nq * 4);
            __nv_bfloat16 h0,h1,h2,h3,l0,l1,l2,l3;
            split_f(v.x,h0,l0); split_f(v.y,h1,l1);
            split_f(v.z,h2,l2); split_f(v.w,h3,l3);
            int nb = nq * 4;
            Bs_hi[nb+0][kk] = h0; Bs_hi[nb+1][kk] = h1;
            Bs_hi[nb+2][kk] = h2; Bs_hi[nb+3][kk] = h3;
            Bs_lo[nb+0][kk] = l0; Bs_lo[nb+1][kk] = l1;
            Bs_lo[nb+2][kk] = l2; Bs_lo[nb+3][kk] = l3;
        }
        __syncthreads();

        #pragma unroll
        for (int ks2 = 0; ks2 < 16; ks2 += 8) {   // word offsets: k = 0, 16
            uint32_t a_hi[2][4], a_lo[2][4];
            #pragma unroll
            for (int mt = 0; mt < 2; mt++) {
                int r = wm + mt * 16 + g;
                a_hi[mt][0] = As_hi[r  ][ks2 + tg];
                a_hi[mt][1] = As_hi[r+8][ks2 + tg];
                a_hi[mt][2] = As_hi[r  ][ks2 + tg + 4];
                a_hi[mt][3] = As_hi[r+8][ks2 + tg + 4];
                a_lo[mt][0] = As_lo[r  ][ks2 + tg];
                a_lo[mt][1] = As_lo[r+8][ks2 + tg];
                a_lo[mt][2] = As_lo[r  ][ks2 + tg + 4];
                a_lo[mt][3] = As_lo[r+8][ks2 + tg + 4];
            }
            #pragma unroll
            for (int nt = 0; nt < 8; nt++) {
                int c = wn + nt * 8 + g;
                int ke = ks2 * 2 + 2 * tg;
                uint32_t b_hi[2], b_lo[2];
                b_hi[0] = *(const uint32_t*)&Bs_hi[c][ke];
                b_hi[1] = *(const uint32_t*)&Bs_hi[c][ke + 8];
                b_lo[0] = *(const uint32_t*)&Bs_lo[c][ke];
                b_lo[1] = *(const uint32_t*)&Bs_lo[c][ke + 8];
                #pragma unroll
                for (int mt = 0; mt < 2; mt++) {
                    mma16816(acc[mt][nt], a_hi[mt], b_hi);
                    mma16816(acc[mt][nt], a_hi[mt], b_lo);
                    mma16816(acc[mt][nt], a_lo[mt], b_hi);
                }
            }
        }
        __syncthreads();
    }

    // ---- epilogue: add bias, store fp32 ----
    #pragma unroll
    for (int mt = 0; mt < 2; mt++) {
        #pragma unroll
        for (int nt = 0; nt < 8; nt++) {
            size_t row = m0 + wm + mt * 16 + g;
            int    col = n0 + wn + nt * 8 + 2 * tg;
            float b0 = bias[col], b1 = bias[col + 1];
            g_xw[row * GATES + col]           = acc[mt][nt][0] + b0;
            g_xw[row * GATES + col + 1]       = acc[mt][nt][1] + b1;
            g_xw[(row + 8) * GATES + col]     = acc[mt][nt][2] + b0;
            g_xw[(row + 8) * GATES + col + 1] = acc[mt][nt][3] + b1;
        }
    }
}

// =====================================================================
// Phase B: persistent recurrent kernel. 128 CTAs, CTA owns 8 hidden cols.
// Per step: gates[64,32] = h(t-1)[64,1024] @ Whslice[1024,32] (split-bf16 mma)
//           + xw slice, then activations; c lives in SMEM; h -> d_out hs slab.
// Grid sync via g_flags spin (single wave guaranteed).
// =====================================================================
#define KC 128   // h K-chunk staged in SMEM

__global__ __launch_bounds__(256, 1)
void lstm_rec_kernel(const float* __restrict__ Wh, float* __restrict__ out,
                     int write_tail)
{
    extern __shared__ char smem_raw[];
    __nv_bfloat16* Ws_hi = (__nv_bfloat16*)smem_raw;        // [32][1026]
    __nv_bfloat16* Ws_lo = Ws_hi + 32 * 1026;               // [32][1026]
    uint32_t* Hs_hi = (uint32_t*)(Ws_lo + 32 * 1026);       // [64][65] (bf16 pairs)
    uint32_t* Hs_lo = Hs_hi + 64 * 65;
    float* gbuf = (float*)(Hs_lo + 64 * 65);                // [64][33]
    float* cbuf = gbuf + 64 * 33;                           // [64][8]

    const int tid  = threadIdx.x;
    const int lane = tid & 31;
    const int warp = tid >> 5;
    const int g    = lane >> 2;
    const int tg   = lane & 3;
    const int wm   = (warp & 3) * 16;   // warp tile 16(m) x 16(n)
    const int wn   = (warp >> 2) * 16;
    const int j0   = blockIdx.x * 8;    // hidden cols owned by this CTA

    // one-time: load W_h slice (cols: gate*1024 + j0 + jj), split to bf16 hi/lo
    for (int i = tid; i < 32 * 1024; i += 256) {
        int col  = i & 31;              // 0..31 = gate*8 + jj
        int k    = i >> 5;              // 0..1023
        int gate = col >> 3;
        float v = Wh[(size_t)k * GATES + gate * HID + j0 + (col & 7)];
        __nv_bfloat16 hi, lo; split_f(v, hi, lo);
        Ws_hi[col * 1026 + k] = hi;
        Ws_lo[col * 1026 + k] = lo;
    }
    __syncthreads();

    for (int t = 0; t < T_STEPS; t++) {
        float acc[2][4] = {{0.f,0.f,0.f,0.f},{0.f,0.f,0.f,0.f}};

        if (t > 0) {
            if (tid == 0) {
                while (*((volatile int*)(g_flags + (t - 1))) != NCTA) { }
            }
            __syncthreads();
            __threadfence();
            const float* hsrc = out + (size_t)(t - 1) * BATCH * HID;

            for (int kc = 0; kc < HID; kc += KC) {
                // stage h chunk [64 x 128] fp32 -> bf16 hi/lo pairs
                #pragma unroll
                for (int i2 = 0; i2 < 8; i2++) {
                    int idx = tid + 256 * i2;    // 0..2047 float4s
                    int m   = idx >> 5;          // 32 float4 per row
                    int kq  = idx & 31;
                    float4 v = *(const float4*)(hsrc + m * HID + kc + kq * 4);
                    __nv_bfloat16 h0,h1,h2,h3,l0,l1,l2,l3;
                    split_f(v.x,h0,l0); split_f(v.y,h1,l1);
                    split_f(v.z,h2,l2); split_f(v.w,h3,l3);
                    Hs_hi[m * 65 + kq*2]     = pack2(h0,h1);
                    Hs_hi[m * 65 + kq*2 + 1] = pack2(h2,h3);
                    Hs_lo[m * 65 + kq*2]     = pack2(l0,l1);
                    Hs_lo[m * 65 + kq*2 + 1] = pack2(l2,l3);
                }
                __syncthreads();

                #pragma unroll
                for (int ks2 = 0; ks2 < 64; ks2 += 8) {   // 8 k16 steps per chunk
                    uint32_t a_hi[4], a_lo[4];
                    int r = wm + g;
                    a_hi[0] = Hs_hi[r * 65 + ks2 + tg];
                    a_hi[1] = Hs_hi[(r + 8) * 65 + ks2 + tg];
                    a_hi[2] = Hs_hi[r * 65 + ks2 + tg + 4];
                    a_hi[3] = Hs_hi[(r + 8) * 65 + ks2 + tg + 4];
                    a_lo[0] = Hs_lo[r * 65 + ks2 + tg];
                    a_lo[1] = Hs_lo[(r + 8) * 65 + ks2 + tg];
                    a_lo[2] = Hs_lo[r * 65 + ks2 + tg + 4];
                    a_lo[3] = Hs_lo[(r + 8) * 65 + ks2 + tg + 4];
                    int kelem = kc + ks2 * 2 + 2 * tg;
                    #pragma unroll
                    for (int nt = 0; nt < 2; nt++) {
                        int c = wn + nt * 8 + g;
                        uint32_t b_hi[2], b_lo[2];
                        b_hi[0] = *(const uint32_t*)&Ws_hi[c * 1026 + kelem];
                        b_hi[1] = *(const uint32_t*)&Ws_hi[c * 1026 + kelem + 8];
                        b_lo[0] = *(const uint32_t*)&Ws_lo[c * 1026 + kelem];
                        b_lo[1] = *(const uint32_t*)&Ws_lo[c * 1026 + kelem + 8];
                        mma16816(acc[nt], a_hi, b_hi);
                        mma16816(acc[nt], a_hi, b_lo);
                        mma16816(acc[nt], a_lo, b_hi);
                    }
                }
                __syncthreads();
            }
        }

        // write h@W_h gates into gbuf (or zero at t==0)
        if (t > 0) {
            #pragma unroll
            for (int nt = 0; nt < 2; nt++) {
                int r = wm + g;
                int c = wn + nt * 8 + 2 * tg;
                gbuf[r * 33 + c]           = acc[nt][0];
                gbuf[r * 33 + c + 1]       = acc[nt][1];
                gbuf[(r + 8) * 33 + c]     = acc[nt][2];
                gbuf[(r + 8) * 33 + c + 1] = acc[nt][3];
            }
        } else {
            for (int i = tid; i < 64 * 33; i += 256) gbuf[i] = 0.f;
        }
        __syncthreads();

        // activations: 512 (b,j) pairs, 2 per thread
        const float* xwt  = g_xw + (size_t)t * BATCH * GATES;
        float*       hdst = out + (size_t)t * BATCH * HID;
        #pragma unroll
        for (int rr = 0; rr < 2; rr++) {
            int p  = tid + 256 * rr;
            int bb = p >> 3;
            int j  = p & 7;
            const float* xr = xwt + (size_t)bb * GATES + j0 + j;
            float gi = gbuf[bb * 33 +  0 + j] + xr[0];
            float gf = gbuf[bb * 33 +  8 + j] + xr[HID];
            float gg = gbuf[bb * 33 + 16 + j] + xr[2 * HID];
            float go = gbuf[bb * 33 + 24 + j] + xr[3 * HID];
            float iv = 1.f / (1.f + expf(-gi));
            float fv = 1.f / (1.f + expf(-gf));
            float gv = tanhf(gg);
            float ov = 1.f / (1.f + expf(-go));
            float cp = (t == 0) ? 0.f : cbuf[bb * 8 + j];
            float cn = fv * cp + iv * gv;
            float hn = ov * tanhf(cn);
            cbuf[bb * 8 + j] = cn;
            hdst[(size_t)bb * HID + j0 + j] = hn;
            if (t == T_STEPS - 1 && write_tail) {
                size_t base = (size_t)T_STEPS * BATCH * HID;
                out[base + (size_t)bb * HID + j0 + j] = hn;                 // hT
                out[base + BATCH * HID + (size_t)bb * HID + j0 + j] = cn;   // cT
            }
        }

        // publish h(t)
        __threadfence();
        __syncthreads();
        if (tid == 0) atomicAdd(g_flags + t, 1);
    }
}

// =====================================================================
extern "C" void kernel_launch(void* const* d_in, const int* in_sizes, int n_in,
                              void* d_out, int out_size)
{
    const float* x  = (const float*)d_in[0];   // [512,64,1024]
    const float* Wx = (const float*)d_in[1];   // [1024,4096]
    const float* Wh = (const float*)d_in[2];   // [1024,4096]
    const float* b  = (const float*)d_in[3];   // [4096]
    float* out = (float*)d_out;

    // Phase A: big GEMM (also re-zeroes g_flags)
    dim3 gridA(GATES / 128, (T_STEPS * BATCH) / 128);   // 32 x 256
    xw_gemm_kernel<<<gridA, 256>>>(x, Wx, b);

    // Phase B: persistent recurrence
    const int smemB = (2 * 32 * 1026) * 2       // Ws hi/lo (bf16)
                    + (2 * 64 * 65) * 4         // Hs hi/lo (u32 pairs)
                    + (64 * 33) * 4             // gbuf
                    + (64 * 8) * 4;             // cbuf
    cudaFuncSetAttribute(lstm_rec_kernel,
                         cudaFuncAttributeMaxDynamicSharedMemorySize, smemB);
    int write_tail = (out_size > T_STEPS * BATCH * HID) ? 1 : 0;
    lstm_rec_kernel<<<NCTA, 256, smemB>>>(Wh, out, write_tail);
}

// round 2
// speedup vs baseline: 1.9309x; 1.9309x over previous
#include <cuda_runtime.h>
#include <cuda_bf16.h>
#include <cstdint>
#include <math.h>

#define T_STEPS 512
#define BATCH   64
#define IN_DIM  1024
#define HID     1024
#define GATES   4096
#define NCTA    128
#define M_TOT   (T_STEPS * BATCH)      // 32768

// ---------------- static scratch ----------------
__device__ __nv_bfloat16 g_Xhi[(size_t)M_TOT * IN_DIM];    // 64 MB
__device__ __nv_bfloat16 g_Xlo[(size_t)M_TOT * IN_DIM];    // 64 MB
__device__ __nv_bfloat16 g_Wthi[(size_t)GATES * IN_DIM];   // 8 MB  [n][k]
__device__ __nv_bfloat16 g_Wtlo[(size_t)GATES * IN_DIM];   // 8 MB
__device__ float    g_xw[(size_t)T_STEPS * BATCH * GATES]; // 512 MB
__device__ uint32_t g_hfrag[(size_t)T_STEPS * 65536];      // 134 MB (mma A-frag layout)
__device__ int      g_flags[T_STEPS];

// ---------------- helpers ----------------
__device__ __forceinline__ void split_f(float v, __nv_bfloat16& hi, __nv_bfloat16& lo) {
    hi = __float2bfloat16(v);
    lo = __float2bfloat16(v - __bfloat162float(hi));
}
__device__ __forceinline__ uint32_t pack2(__nv_bfloat16 a, __nv_bfloat16 b) {
    __nv_bfloat162 t = __halves2bfloat162(a, b);
    return *reinterpret_cast<uint32_t*>(&t);
}
__device__ __forceinline__ void mma16816(float* c, const uint32_t* a, const uint32_t* b) {
    asm volatile(
        "mma.sync.aligned.m16n8k16.row.col.f32.bf16.bf16.f32 "
        "{%0,%1,%2,%3}, {%4,%5,%6,%7}, {%8,%9}, {%0,%1,%2,%3};\n"
        : "+f"(c[0]), "+f"(c[1]), "+f"(c[2]), "+f"(c[3])
        : "r"(a[0]), "r"(a[1]), "r"(a[2]), "r"(a[3]), "r"(b[0]), "r"(b[1]));
}
__device__ __forceinline__ void cpasync16(void* s, const void* g) {
    uint32_t sa = (uint32_t)__cvta_generic_to_shared(s);
    asm volatile("cp.async.cg.shared.global [%0], [%1], 16;\n" :: "r"(sa), "l"(g));
}
#define CP_COMMIT() asm volatile("cp.async.commit_group;\n")
#define CP_WAIT1()  asm volatile("cp.async.wait_group 1;\n")

// =====================================================================
// Converters (bandwidth-bound, run once per launch)
// =====================================================================
__global__ __launch_bounds__(256)
void convert_x_kernel(const float* __restrict__ X)
{
    if (blockIdx.x == 0) {           // replay-safe flag reset
        if (threadIdx.x < 256) { g_flags[threadIdx.x] = 0; g_flags[threadIdx.x + 256] = 0; }
    }
    size_t idx = (size_t)blockIdx.x * 256 + threadIdx.x;      // float4 index
    float4 v = ((const float4*)X)[idx];
    __nv_bfloat16 h0,h1,h2,h3,l0,l1,l2,l3;
    split_f(v.x,h0,l0); split_f(v.y,h1,l1); split_f(v.z,h2,l2); split_f(v.w,h3,l3);
    uint2 hi = make_uint2(pack2(h0,h1), pack2(h2,h3));
    uint2 lo = make_uint2(pack2(l0,l1), pack2(l2,l3));
    ((uint2*)g_Xhi)[idx] = hi;
    ((uint2*)g_Xlo)[idx] = lo;
}

__global__ __launch_bounds__(256)
void convert_w_kernel(const float* __restrict__ W)   // W [k=1024][n=4096] -> [n][k] bf16 hi/lo
{
    __shared__ float st[32][33];
    const int n0 = blockIdx.x * 32;
    const int k0 = blockIdx.y * 32;
    const int tid = threadIdx.x;
    #pragma unroll
    for (int i = 0; i < 4; i++) {
        int id = tid + 256 * i;
        int kr = id >> 5, nc = id & 31;
        st[kr][nc] = W[(size_t)(k0 + kr) * GATES + n0 + nc];
    }
    __syncthreads();
    #pragma unroll
    for (int i = 0; i < 2; i++) {
        int id = tid + 256 * i;
        int nr = id >> 4, kc = id & 15;
        float v0 = st[2 * kc][nr], v1 = st[2 * kc + 1][nr];
        __nv_bfloat16 h0,h1,l0,l1;
        split_f(v0,h0,l0); split_f(v1,h1,l1);
        size_t o = (size_t)(n0 + nr) * (IN_DIM / 2) + (k0 >> 1) + kc;
        ((uint32_t*)g_Wthi)[o] = pack2(h0,h1);
        ((uint32_t*)g_Wtlo)[o] = pack2(l0,l1);
    }
}

// =====================================================================
// Phase A: g_xw = x @ W_x + b   (M=32768, N=4096, K=1024)
// 128x128 tile, BK=32, 3-stage cp.async, split-bf16 3-term mma
// =====================================================================
#define STG_BYTES 40960      // per stage: Ahi/Alo/Bhi/Blo each 128*40 halves

__global__ __launch_bounds__(256, 1)
void xw_gemm_kernel(const float* __restrict__ bias)
{
    extern __shared__ char sm[];
    const int tid  = threadIdx.x;
    const int lane = tid & 31;
    const int warp = tid >> 5;
    const int g    = lane >> 2;
    const int tg   = lane & 3;
    const int wm   = (warp & 3) * 32;
    const int wn   = (warp >> 2) * 64;
    const size_t m0 = (size_t)blockIdx.y * 128;
    const int    n0 = blockIdx.x * 128;

    float acc[2][8][4];
    #pragma unroll
    for (int i = 0; i < 2; i++)
        #pragma unroll
        for (int j = 0; j < 8; j++)
            #pragma unroll
            for (int k = 0; k < 4; k++) acc[i][j][k] = 0.f;

    auto load_stage = [&](int s, int kk) {
        const int k0 = kk * 32;
        char* base = sm + s * STG_BYTES;
        __nv_bfloat16* sAhi = (__nv_bfloat16*)(base);
        __nv_bfloat16* sAlo = (__nv_bfloat16*)(base + 10240);
        __nv_bfloat16* sBhi = (__nv_bfloat16*)(base + 20480);
        __nv_bfloat16* sBlo = (__nv_bfloat16*)(base + 30720);
        #pragma unroll
        for (int i = 0; i < 2; i++) {
            int id  = tid + 256 * i;
            int row = id >> 2, ch = id & 3;
            int so  = row * 40 + ch * 8;
            size_t gA = (m0 + row) * (size_t)IN_DIM + k0 + ch * 8;
            size_t gB = (size_t)(n0 + row) * IN_DIM + k0 + ch * 8;
            cpasync16(sAhi + so, g_Xhi + gA);
            cpasync16(sAlo + so, g_Xlo + gA);
            cpasync16(sBhi + so, g_Wthi + gB);
            cpasync16(sBlo + so, g_Wtlo + gB);
        }
        CP_COMMIT();
    };

    load_stage(0, 0);
    load_stage(1, 1);

    for (int it = 0; it < 32; ++it) {
        CP_WAIT1();
        __syncthreads();
        if (it + 2 < 32) load_stage((it + 2) % 3, it + 2);
        else CP_COMMIT();                       // keep group count uniform

        const char* base = sm + (it % 3) * STG_BYTES;
        const uint32_t* Ah = (const uint32_t*)(base);
        const uint32_t* Al = (const uint32_t*)(base + 10240);
        const uint32_t* Bh = (const uint32_t*)(base + 20480);
        const uint32_t* Bl = (const uint32_t*)(base + 30720);

        #pragma unroll
        for (int ks = 0; ks < 16; ks += 8) {
            uint32_t ahi[2][4], alo[2][4];
            #pragma unroll
            for (int mt = 0; mt < 2; mt++) {
                int r = wm + mt * 16 + g;
                ahi[mt][0] = Ah[r * 20 + ks + tg];
                ahi[mt][1] = Ah[(r + 8) * 20 + ks + tg];
                ahi[mt][2] = Ah[r * 20 + ks + tg + 4];
                ahi[mt][3] = Ah[(r + 8) * 20 + ks + tg + 4];
                alo[mt][0] = Al[r * 20 + ks + tg];
                alo[mt][1] = Al[(r + 8) * 20 + ks + tg];
                alo[mt][2] = Al[r * 20 + ks + tg + 4];
                alo[mt][3] = Al[(r + 8) * 20 + ks + tg + 4];
            }
            #pragma unroll
            for (int nt = 0; nt < 8; nt++) {
                int c = wn + nt * 8 + g;
                uint32_t bh[2] = { Bh[c * 20 + ks + tg], Bh[c * 20 + ks + tg + 4] };
                uint32_t bl[2] = { Bl[c * 20 + ks + tg], Bl[c * 20 + ks + tg + 4] };
                #pragma unroll
                for (int mt = 0; mt < 2; mt++) {
                    mma16816(acc[mt][nt], ahi[mt], bh);
                    mma16816(acc[mt][nt], ahi[mt], bl);
                    mma16816(acc[mt][nt], alo[mt], bh);
                }
            }
        }
        __syncthreads();
    }

    #pragma unroll
    for (int mt = 0; mt < 2; mt++) {
        #pragma unroll
        for (int nt = 0; nt < 8; nt++) {
            size_t row = m0 + wm + mt * 16 + g;
            int    col = n0 + wn + nt * 8 + 2 * tg;
            float b0 = bias[col], b1 = bias[col + 1];
            g_xw[row * GATES + col]           = acc[mt][nt][0] + b0;
            g_xw[row * GATES + col + 1]       = acc[mt][nt][1] + b1;
            g_xw[(row + 8) * GATES + col]     = acc[mt][nt][2] + b0;
            g_xw[(row + 8) * GATES + col + 1] = acc[mt][nt][3] + b1;
        }
    }
}

// =====================================================================
// Phase B: persistent recurrence. CTA owns 8 hidden cols (N=32 gates).
// h exchanged through g_hfrag in mma A-fragment layout (bf16 hi/lo),
// W_h held in SMEM in fragment-friendly layout (1 LDS.128 per B-frag).
// =====================================================================
#define WS_PITCH 1040        // u32 per W column block (padded: 1040 % 32 == 16)

__global__ __launch_bounds__(256, 1)
void lstm_rec_kernel(const float* __restrict__ Wh, float* __restrict__ out,
                     int write_tail)
{
    extern __shared__ char smraw[];
    uint32_t* Wsf  = (uint32_t*)smraw;                    // 32 * 1040 u32 = 133120 B
    float*    gbuf = (float*)(Wsf + 32 * WS_PITCH);       // [64][33]

    const int tid  = threadIdx.x;
    const int lane = tid & 31;
    const int warp = tid >> 5;
    const int g    = lane >> 2;
    const int tg   = lane & 3;
    const int wm   = (warp & 3) * 16;
    const int wn   = (warp >> 2) * 16;      // {0,16}
    const int mtw  = warp & 3;
    const int j0   = blockIdx.x * 8;

    // ---- one-time: W_h slice -> SMEM fragment layout (hi,hi,lo,lo per uint4) ----
    for (int i = tid; i < 32 * 1024; i += 256) {
        int c = i & 31;                 // 0..31 = gate*8 + jj
        int k = i >> 5;                 // 0..1023
        int col = (c >> 3) * HID + j0 + (c & 7);
        float v = Wh[(size_t)k * GATES + col];
        __nv_bfloat16 hi, lo; split_f(v, hi, lo);
        int kt = k >> 4, t4 = (k >> 1) & 3, w = (k >> 3) & 1, hf = k & 1;
        int word = c * WS_PITCH + kt * 16 + t4 * 4 + w;
        ((__nv_bfloat16*)Wsf)[word * 2 + hf]       = hi;
        ((__nv_bfloat16*)Wsf)[(word + 2) * 2 + hf] = lo;
    }
    __syncthreads();

    float creg[2] = {0.f, 0.f};          // c-state lives in registers

    for (int t = 0; t < T_STEPS; t++) {
        // prefetch xw slice for this step (independent of the spin)
        float xg[2][4];
        #pragma unroll
        for (int rr = 0; rr < 2; rr++) {
            int p  = tid + 256 * rr;
            int bb = p >> 3, j = p & 7;
            const float* xr = g_xw + (size_t)t * BATCH * GATES + (size_t)bb * GATES + j0 + j;
            xg[rr][0] = xr[0];
            xg[rr][1] = xr[HID];
            xg[rr][2] = xr[2 * HID];
            xg[rr][3] = xr[3 * HID];
        }

        float acc[2][4] = {{0.f,0.f,0.f,0.f},{0.f,0.f,0.f,0.f}};

        if (t > 0) {
            if (tid == 0) {
                while (*((volatile int*)(g_flags + (t - 1))) != NCTA) { }
            }
            __syncthreads();
            __threadfence();

            const uint32_t* ab = g_hfrag + (size_t)(t - 1) * 65536 + mtw * 256 + lane * 8;

            uint4 H[4], L[4];
            #pragma unroll
            for (int q = 0; q < 4; q++) {
                H[q] = *(const uint4*)(ab + q * 1024);
                L[q] = *(const uint4*)(ab + q * 1024 + 4);
            }
            #pragma unroll 4
            for (int kt = 0; kt < 64; kt++) {
                int s = kt & 3;
                uint32_t ah[4] = {H[s].x, H[s].y, H[s].z, H[s].w};
                uint32_t al[4] = {L[s].x, L[s].y, L[s].z, L[s].w};
                #pragma unroll
                for (int nt = 0; nt < 2; nt++) {
                    int c = wn + nt * 8 + g;
                    uint4 bf = *(const uint4*)(Wsf + c * WS_PITCH + kt * 16 + tg * 4);
                    uint32_t bh[2] = {bf.x, bf.y};
                    uint32_t bl[2] = {bf.z, bf.w};
                    mma16816(acc[nt], ah, bh);
                    mma16816(acc[nt], ah, bl);
                    mma16816(acc[nt], al, bh);
                }
                if (kt + 4 < 64) {
                    H[s] = *(const uint4*)(ab + (kt + 4) * 1024);
                    L[s] = *(const uint4*)(ab + (kt + 4) * 1024 + 4);
                }
            }

            #pragma unroll
            for (int nt = 0; nt < 2; nt++) {
                int r = wm + g;
                int c = wn + nt * 8 + 2 * tg;
                gbuf[r * 33 + c]           = acc[nt][0];
                gbuf[r * 33 + c + 1]       = acc[nt][1];
                gbuf[(r + 8) * 33 + c]     = acc[nt][2];
                gbuf[(r + 8) * 33 + c + 1] = acc[nt][3];
            }
        } else {
            for (int i = tid; i < 64 * 33; i += 256) gbuf[i] = 0.f;
        }
        __syncthreads();

        // ---- activations + h output + fragment publish ----
        float* hdst = out + (size_t)t * BATCH * HID;
        #pragma unroll
        for (int rr = 0; rr < 2; rr++) {
            int p  = tid + 256 * rr;
            int bb = p >> 3, j = p & 7;
            int jg = j0 + j;
            float gi = gbuf[bb * 33 +  0 + j] + xg[rr][0];
            float gf = gbuf[bb * 33 +  8 + j] + xg[rr][1];
            float gg = gbuf[bb * 33 + 16 + j] + xg[rr][2];
            float go = gbuf[bb * 33 + 24 + j] + xg[rr][3];
            float iv = 1.f / (1.f + expf(-gi));
            float fv = 1.f / (1.f + expf(-gf));
            float gv = tanhf(gg);
            float ov = 1.f / (1.f + expf(-go));
            float cn = fv * creg[rr] + iv * gv;
            float hn = ov * tanhf(cn);
            creg[rr] = cn;
            hdst[(size_t)bb * HID + jg] = hn;

            // publish h in A-fragment layout (pairs of k-adjacent threads)
            __nv_bfloat16 hh, hl; split_f(hn, hh, hl);
            uint32_t mypk = pack2(hh, hl);
            uint32_t pp   = __shfl_xor_sync(0xffffffffu, mypk, 1);
            if ((tid & 1) == 0) {
                uint32_t hi_pair = (mypk & 0xffffu) | (pp << 16);
                uint32_t lo_pair = (mypk >> 16)     | (pp & 0xffff0000u);
                int kt = jg >> 4, kk = jg & 15, mt = bb >> 4, r = bb & 15;
                int fl = (r & 7) * 4 + ((kk >> 1) & 3);
                int rg = ((kk >> 3) << 1) | (r >> 3);
                size_t fb = (size_t)t * 65536 + kt * 1024 + mt * 256 + fl * 8 + rg;
                g_hfrag[fb]     = hi_pair;
                g_hfrag[fb + 4] = lo_pair;
            }
            if (t == T_STEPS - 1 && write_tail) {
                size_t base = (size_t)T_STEPS * BATCH * HID;
                out[base + (size_t)bb * HID + jg] = hn;
                out[base + BATCH * HID + (size_t)bb * HID + jg] = cn;
            }
        }

        __threadfence();
        __syncthreads();
        if (tid == 0) atomicAdd(g_flags + t, 1);
    }
}

// =====================================================================
extern "C" void kernel_launch(void* const* d_in, const int* in_sizes, int n_in,
                              void* d_out, int out_size)
{
    const float* x  = (const float*)d_in[0];   // [512,64,1024]
    const float* Wx = (const float*)d_in[1];   // [1024,4096]
    const float* Wh = (const float*)d_in[2];   // [1024,4096]
    const float* b  = (const float*)d_in[3];   // [4096]
    float* out = (float*)d_out;

    // converters (also reset flags)
    convert_x_kernel<<<(M_TOT * IN_DIM / 4) / 256, 256>>>(x);
    convert_w_kernel<<<dim3(GATES / 32, IN_DIM / 32), 256>>>(Wx);

    // Phase A
    const int smemA = 3 * STG_BYTES;   // 122880
    cudaFuncSetAttribute(xw_gemm_kernel,
                         cudaFuncAttributeMaxDynamicSharedMemorySize, smemA);
    dim3 gridA(GATES / 128, M_TOT / 128);   // 32 x 256
    xw_gemm_kernel<<<gridA, 256, smemA>>>(b);

    // Phase B
    const int smemB = 32 * WS_PITCH * 4 + 64 * 33 * 4;   // 133120 + 8448
    cudaFuncSetAttribute(lstm_rec_kernel,
                         cudaFuncAttributeMaxDynamicSharedMemorySize, smemB);
    int write_tail = (out_size > T_STEPS * BATCH * HID) ? 1 : 0;
    lstm_rec_kernel<<<NCTA, 256, smemB>>>(Wh, out, write_tail);
}

// round 3
// speedup vs baseline: 1.9413x; 1.0054x over previous
#include <cuda_runtime.h>
#include <cuda_bf16.h>
#include <cstdint>
#include <math.h>

#define T_STEPS 512
#define BATCH   64
#define IN_DIM  1024
#define HID     1024
#define GATES   4096
#define NCTA    128
#define M_TOT   (T_STEPS * BATCH)      // 32768

// ---------------- static scratch ----------------
__device__ __nv_bfloat16 g_Xhi[(size_t)M_TOT * IN_DIM];    // 64 MB
__device__ __nv_bfloat16 g_Xlo[(size_t)M_TOT * IN_DIM];    // 64 MB
__device__ __nv_bfloat16 g_Wthi[(size_t)GATES * IN_DIM];   // 8 MB  [n][k]
__device__ __nv_bfloat16 g_Wtlo[(size_t)GATES * IN_DIM];   // 8 MB
__device__ float    g_xw[(size_t)T_STEPS * BATCH * GATES]; // 512 MB
__device__ uint32_t g_hfrag[(size_t)T_STEPS * 65536];      // 134 MB (mma A-frag layout)
__device__ int      g_flags[T_STEPS];

// ---------------- helpers ----------------
__device__ __forceinline__ void split_f(float v, __nv_bfloat16& hi, __nv_bfloat16& lo) {
    hi = __float2bfloat16(v);
    lo = __float2bfloat16(v - __bfloat162float(hi));
}
__device__ __forceinline__ uint32_t pack2(__nv_bfloat16 a, __nv_bfloat16 b) {
    __nv_bfloat162 t = __halves2bfloat162(a, b);
    return *reinterpret_cast<uint32_t*>(&t);
}
__device__ __forceinline__ void mma16816(float* c, const uint32_t* a, const uint32_t* b) {
    asm volatile(
        "mma.sync.aligned.m16n8k16.row.col.f32.bf16.bf16.f32 "
        "{%0,%1,%2,%3}, {%4,%5,%6,%7}, {%8,%9}, {%0,%1,%2,%3};\n"
        : "+f"(c[0]), "+f"(c[1]), "+f"(c[2]), "+f"(c[3])
        : "r"(a[0]), "r"(a[1]), "r"(a[2]), "r"(a[3]), "r"(b[0]), "r"(b[1]));
}
__device__ __forceinline__ void ldsm_x4(uint32_t* r, uint32_t saddr) {
    asm volatile("ldmatrix.sync.aligned.m8n8.x4.shared.b16 {%0,%1,%2,%3}, [%4];\n"
        : "=r"(r[0]), "=r"(r[1]), "=r"(r[2]), "=r"(r[3]) : "r"(saddr));
}
__device__ __forceinline__ void cpasync16(uint32_t s, const void* g) {
    asm volatile("cp.async.cg.shared.global [%0], [%1], 16;\n" :: "r"(s), "l"(g));
}
#define CP_COMMIT() asm volatile("cp.async.commit_group;\n")
#define CP_WAIT1()  asm volatile("cp.async.wait_group 1;\n")

// =====================================================================
// Converters
// =====================================================================
__global__ __launch_bounds__(256)
void convert_x_kernel(const float* __restrict__ X)
{
    if (blockIdx.x == 0) {
        if (threadIdx.x < 256) { g_flags[threadIdx.x] = 0; g_flags[threadIdx.x + 256] = 0; }
    }
    size_t idx = (size_t)blockIdx.x * 256 + threadIdx.x;
    float4 v = ((const float4*)X)[idx];
    __nv_bfloat16 h0,h1,h2,h3,l0,l1,l2,l3;
    split_f(v.x,h0,l0); split_f(v.y,h1,l1); split_f(v.z,h2,l2); split_f(v.w,h3,l3);
    ((uint2*)g_Xhi)[idx] = make_uint2(pack2(h0,h1), pack2(h2,h3));
    ((uint2*)g_Xlo)[idx] = make_uint2(pack2(l0,l1), pack2(l2,l3));
}

__global__ __launch_bounds__(256)
void convert_w_kernel(const float* __restrict__ W)   // [k][n] -> [n][k] bf16 hi/lo
{
    __shared__ float st[32][33];
    const int n0 = blockIdx.x * 32;
    const int k0 = blockIdx.y * 32;
    const int tid = threadIdx.x;
    #pragma unroll
    for (int i = 0; i < 4; i++) {
        int id = tid + 256 * i;
        int kr = id >> 5, nc = id & 31;
        st[kr][nc] = W[(size_t)(k0 + kr) * GATES + n0 + nc];
    }
    __syncthreads();
    #pragma unroll
    for (int i = 0; i < 2; i++) {
        int id = tid + 256 * i;
        int nr = id >> 4, kc = id & 15;
        float v0 = st[2 * kc][nr], v1 = st[2 * kc + 1][nr];
        __nv_bfloat16 h0,h1,l0,l1;
        split_f(v0,h0,l0); split_f(v1,h1,l1);
        size_t o = (size_t)(n0 + nr) * (IN_DIM / 2) + (k0 >> 1) + kc;
        ((uint32_t*)g_Wthi)[o] = pack2(h0,h1);
        ((uint32_t*)g_Wtlo)[o] = pack2(l0,l1);
    }
}

// =====================================================================
// Phase A: g_xw = x @ W_x + b   (M=32768, N=4096, K=1024)
// CTA tile 128(M) x 256(N), BK=32, 3-stage cp.async, ldmatrix fragments,
// split-bf16 3-term mma. 256 threads, warp tile 32m x 128n.
// =====================================================================
#define STG_BYTES 61440
#define OFF_ALO   10240
#define OFF_BHI   20480
#define OFF_BLO   40960
#define PITCH     40        // halves per smem row (80 B)

__global__ __launch_bounds__(256, 1)
void xw_gemm_kernel(const float* __restrict__ bias)
{
    extern __shared__ char sm[];
    const uint32_t smu = (uint32_t)__cvta_generic_to_shared(sm);

    const int tid  = threadIdx.x;
    const int lane = tid & 31;
    const int warp = tid >> 5;
    const int g    = lane >> 2;
    const int tg   = lane & 3;
    const int wm   = (warp & 3) * 32;
    const int wn   = (warp >> 2) * 128;
    const size_t m0 = (size_t)blockIdx.y * 128;
    const int    n0 = blockIdx.x * 256;

    // ldmatrix per-lane source row/col within a 16x16 block
    const int rA = (lane & 7) | (((lane >> 3) & 1) << 3);
    const int cA = (lane >> 4) * 8;

    float acc[2][16][4];
    #pragma unroll
    for (int a = 0; a < 2; a++)
        #pragma unroll
        for (int b2 = 0; b2 < 16; b2++)
            #pragma unroll
            for (int c = 0; c < 4; c++) acc[a][b2][c] = 0.f;

    auto load_stage = [&](int s, int kk) {
        const int k0 = kk * 32;
        const uint32_t base = smu + s * STG_BYTES;
        // A: 1024 16B-chunks (hi+lo), B: 2048
        #pragma unroll
        for (int i = 0; i < 4; i++) {
            int id  = tid + 256 * i;            // 0..1023
            int arr = id >> 9;                  // 0 hi, 1 lo
            int rc  = id & 511;
            int row = rc >> 2, ch = rc & 3;
            const __nv_bfloat16* src = (arr ? g_Xlo : g_Xhi) + (m0 + row) * (size_t)IN_DIM + k0 + ch * 8;
            cpasync16(base + arr * OFF_ALO + (row * PITCH + ch * 8) * 2, src);
        }
        #pragma unroll
        for (int i = 0; i < 8; i++) {
            int id  = tid + 256 * i;            // 0..2047
            int arr = id >> 10;
            int rc  = id & 1023;
            int row = rc >> 2, ch = rc & 3;
            const __nv_bfloat16* src = (arr ? g_Wtlo : g_Wthi) + (size_t)(n0 + row) * IN_DIM + k0 + ch * 8;
            cpasync16(base + OFF_BHI + arr * (OFF_BLO - OFF_BHI) + (row * PITCH + ch * 8) * 2, src);
        }
        CP_COMMIT();
    };

    load_stage(0, 0);
    load_stage(1, 1);

    for (int it = 0; it < 32; ++it) {
        CP_WAIT1();
        __syncthreads();
        if (it + 2 < 32) load_stage((it + 2) % 3, it + 2);
        else CP_COMMIT();

        const uint32_t sb = smu + (it % 3) * STG_BYTES;

        #pragma unroll
        for (int ks = 0; ks < 2; ks++) {
            uint32_t ah[2][4], al[2][4];
            #pragma unroll
            for (int mt = 0; mt < 2; mt++) {
                uint32_t ao = ((wm + mt * 16 + rA) * PITCH + ks * 16 + cA) * 2;
                ldsm_x4(ah[mt], sb + ao);
                ldsm_x4(al[mt], sb + OFF_ALO + ao);
            }
            #pragma unroll
            for (int q = 0; q < 8; q++) {
                uint32_t bh[4], bl[4];
                uint32_t bo = ((wn + q * 16 + rA) * PITCH + ks * 16 + cA) * 2;
                ldsm_x4(bh, sb + OFF_BHI + bo);
                ldsm_x4(bl, sb + OFF_BLO + bo);
                uint32_t b0h[2] = {bh[0], bh[2]}, b0l[2] = {bl[0], bl[2]};
                uint32_t b1h[2] = {bh[1], bh[3]}, b1l[2] = {bl[1], bl[3]};
                #pragma unroll
                for (int mt = 0; mt < 2; mt++) {
                    mma16816(acc[mt][2*q],   ah[mt], b0h);
                    mma16816(acc[mt][2*q],   ah[mt], b0l);
                    mma16816(acc[mt][2*q],   al[mt], b0h);
                    mma16816(acc[mt][2*q+1], ah[mt], b1h);
                    mma16816(acc[mt][2*q+1], ah[mt], b1l);
                    mma16816(acc[mt][2*q+1], al[mt], b1h);
                }
            }
        }
    }

    // epilogue
    #pragma unroll
    for (int mt = 0; mt < 2; mt++) {
        #pragma unroll
        for (int nt = 0; nt < 16; nt++) {
            size_t row = m0 + wm + mt * 16 + g;
            int    col = n0 + wn + nt * 8 + 2 * tg;
            float b0 = bias[col], b1 = bias[col + 1];
            float2 v0 = make_float2(acc[mt][nt][0] + b0, acc[mt][nt][1] + b1);
            float2 v1 = make_float2(acc[mt][nt][2] + b0, acc[mt][nt][3] + b1);
            *(float2*)(g_xw + row * GATES + col)       = v0;
            *(float2*)(g_xw + (row + 8) * GATES + col) = v1;
        }
    }
}

// =====================================================================
// Phase B: persistent recurrence (unchanged from round 2)
// =====================================================================
#define WS_PITCH 1040

__global__ __launch_bounds__(256, 1)
void lstm_rec_kernel(const float* __restrict__ Wh, float* __restrict__ out,
                     int write_tail)
{
    extern __shared__ char smraw[];
    uint32_t* Wsf  = (uint32_t*)smraw;
    float*    gbuf = (float*)(Wsf + 32 * WS_PITCH);

    const int tid  = threadIdx.x;
    const int lane = tid & 31;
    const int warp = tid >> 5;
    const int g    = lane >> 2;
    const int tg   = lane & 3;
    const int wm   = (warp & 3) * 16;
    const int wn   = (warp >> 2) * 16;
    const int mtw  = warp & 3;
    const int j0   = blockIdx.x * 8;

    for (int i = tid; i < 32 * 1024; i += 256) {
        int c = i & 31;
        int k = i >> 5;
        int col = (c >> 3) * HID + j0 + (c & 7);
        float v = Wh[(size_t)k * GATES + col];
        __nv_bfloat16 hi, lo; split_f(v, hi, lo);
        int kt = k >> 4, t4 = (k >> 1) & 3, w = (k >> 3) & 1, hf = k & 1;
        int word = c * WS_PITCH + kt * 16 + t4 * 4 + w;
        ((__nv_bfloat16*)Wsf)[word * 2 + hf]       = hi;
        ((__nv_bfloat16*)Wsf)[(word + 2) * 2 + hf] = lo;
    }
    __syncthreads();

    float creg[2] = {0.f, 0.f};

    for (int t = 0; t < T_STEPS; t++) {
        float xg[2][4];
        #pragma unroll
        for (int rr = 0; rr < 2; rr++) {
            int p  = tid + 256 * rr;
            int bb = p >> 3, j = p & 7;
            const float* xr = g_xw + (size_t)t * BATCH * GATES + (size_t)bb * GATES + j0 + j;
            xg[rr][0] = xr[0];
            xg[rr][1] = xr[HID];
            xg[rr][2] = xr[2 * HID];
            xg[rr][3] = xr[3 * HID];
        }

        float acc[2][4] = {{0.f,0.f,0.f,0.f},{0.f,0.f,0.f,0.f}};

        if (t > 0) {
            if (tid == 0) {
                while (*((volatile int*)(g_flags + (t - 1))) != NCTA) { }
            }
            __syncthreads();
            __threadfence();

            const uint32_t* ab = g_hfrag + (size_t)(t - 1) * 65536 + mtw * 256 + lane * 8;

            uint4 H[4], L[4];
            #pragma unroll
            for (int q = 0; q < 4; q++) {
                H[q] = *(const uint4*)(ab + q * 1024);
                L[q] = *(const uint4*)(ab + q * 1024 + 4);
            }
            #pragma unroll 4
            for (int kt = 0; kt < 64; kt++) {
                int s = kt & 3;
                uint32_t ah[4] = {H[s].x, H[s].y, H[s].z, H[s].w};
                uint32_t al[4] = {L[s].x, L[s].y, L[s].z, L[s].w};
                #pragma unroll
                for (int nt = 0; nt < 2; nt++) {
                    int c = wn + nt * 8 + g;
                    uint4 bf = *(const uint4*)(Wsf + c * WS_PITCH + kt * 16 + tg * 4);
                    uint32_t bh[2] = {bf.x, bf.y};
                    uint32_t bl[2] = {bf.z, bf.w};
                    mma16816(acc[nt], ah, bh);
                    mma16816(acc[nt], ah, bl);
                    mma16816(acc[nt], al, bh);
                }
                if (kt + 4 < 64) {
                    H[s] = *(const uint4*)(ab + (kt + 4) * 1024);
                    L[s] = *(const uint4*)(ab + (kt + 4) * 1024 + 4);
                }
            }

            #pragma unroll
            for (int nt = 0; nt < 2; nt++) {
                int r = wm + g;
                int c = wn + nt * 8 + 2 * tg;
                gbuf[r * 33 + c]           = acc[nt][0];
                gbuf[r * 33 + c + 1]       = acc[nt][1];
                gbuf[(r + 8) * 33 + c]     = acc[nt][2];
                gbuf[(r + 8) * 33 + c + 1] = acc[nt][3];
            }
        } else {
            for (int i = tid; i < 64 * 33; i += 256) gbuf[i] = 0.f;
        }
        __syncthreads();

        float* hdst = out + (size_t)t * BATCH * HID;
        #pragma unroll
        for (int rr = 0; rr < 2; rr++) {
            int p  = tid + 256 * rr;
            int bb = p >> 3, j = p & 7;
            int jg = j0 + j;
            float gi = gbuf[bb * 33 +  0 + j] + xg[rr][0];
            float gf = gbuf[bb * 33 +  8 + j] + xg[rr][1];
            float gg = gbuf[bb * 33 + 16 + j] + xg[rr][2];
            float go = gbuf[bb * 33 + 24 + j] + xg[rr][3];
            float iv = 1.f / (1.f + expf(-gi));
            float fv = 1.f / (1.f + expf(-gf));
            float gv = tanhf(gg);
            float ov = 1.f / (1.f + expf(-go));
            float cn = fv * creg[rr] + iv * gv;
            float hn = ov * tanhf(cn);
            creg[rr] = cn;
            hdst[(size_t)bb * HID + jg] = hn;

            __nv_bfloat16 hh, hl; split_f(hn, hh, hl);
            uint32_t mypk = pack2(hh, hl);
            uint32_t pp   = __shfl_xor_sync(0xffffffffu, mypk, 1);
            if ((tid & 1) == 0) {
                uint32_t hi_pair = (mypk & 0xffffu) | (pp << 16);
                uint32_t lo_pair = (mypk >> 16)     | (pp & 0xffff0000u);
                int kt = jg >> 4, kk = jg & 15, mt = bb >> 4, r = bb & 15;
                int fl = (r & 7) * 4 + ((kk >> 1) & 3);
                int rg = ((kk >> 3) << 1) | (r >> 3);
                size_t fb = (size_t)t * 65536 + kt * 1024 + mt * 256 + fl * 8 + rg;
                g_hfrag[fb]     = hi_pair;
                g_hfrag[fb + 4] = lo_pair;
            }
            if (t == T_STEPS - 1 && write_tail) {
                size_t base = (size_t)T_STEPS * BATCH * HID;
                out[base + (size_t)bb * HID + jg] = hn;
                out[base + BATCH * HID + (size_t)bb * HID + jg] = cn;
            }
        }

        __threadfence();
        __syncthreads();
        if (tid == 0) atomicAdd(g_flags + t, 1);
    }
}

// =====================================================================
extern "C" void kernel_launch(void* const* d_in, const int* in_sizes, int n_in,
                              void* d_out, int out_size)
{
    const float* x  = (const float*)d_in[0];
    const float* Wx = (const float*)d_in[1];
    const float* Wh = (const float*)d_in[2];
    const float* b  = (const float*)d_in[3];
    float* out = (float*)d_out;

    convert_x_kernel<<<(M_TOT * IN_DIM / 4) / 256, 256>>>(x);
    convert_w_kernel<<<dim3(GATES / 32, IN_DIM / 32), 256>>>(Wx);

    const int smemA = 3 * STG_BYTES;   // 184320
    cudaFuncSetAttribute(xw_gemm_kernel,
                         cudaFuncAttributeMaxDynamicSharedMemorySize, smemA);
    dim3 gridA(GATES / 256, M_TOT / 128);   // 16 x 256
    xw_gemm_kernel<<<gridA, 256, smemA>>>(b);

    const int smemB = 32 * WS_PITCH * 4 + 64 * 33 * 4;
    cudaFuncSetAttribute(lstm_rec_kernel,
                         cudaFuncAttributeMaxDynamicSharedMemorySize, smemB);
    int write_tail = (out_size > T_STEPS * BATCH * HID) ? 1 : 0;
    lstm_rec_kernel<<<NCTA, 256, smemB>>>(Wh, out, write_tail);
}

// round 4
// speedup vs baseline: 2.6569x; 1.3686x over previous
#include <cuda_runtime.h>
#include <cuda_bf16.h>
#include <cstdint>
#include <math.h>

#define T_STEPS 512
#define BATCH   64
#define IN_DIM  1024
#define HID     1024
#define GATES   4096
#define NCTA    128
#define M_TOT   (T_STEPS * BATCH)      // 32768

// ---------------- static scratch ----------------
__device__ __nv_bfloat16 g_Xhi[(size_t)M_TOT * IN_DIM];    // 64 MB
__device__ __nv_bfloat16 g_Xlo[(size_t)M_TOT * IN_DIM];    // 64 MB
__device__ __nv_bfloat16 g_Wthi[(size_t)GATES * IN_DIM];   // 8 MB  [n][k]
__device__ __nv_bfloat16 g_Wtlo[(size_t)GATES * IN_DIM];   // 8 MB
__device__ float    g_xw[(size_t)T_STEPS * BATCH * GATES]; // 512 MB
__device__ uint32_t g_hfrag[(size_t)T_STEPS * 65536];      // 134 MB (mma A-frag layout)
__device__ int      g_flags[T_STEPS];

// ---------------- helpers ----------------
__device__ __forceinline__ void split_f(float v, __nv_bfloat16& hi, __nv_bfloat16& lo) {
    hi = __float2bfloat16(v);
    lo = __float2bfloat16(v - __bfloat162float(hi));
}
__device__ __forceinline__ uint32_t pack2(__nv_bfloat16 a, __nv_bfloat16 b) {
    __nv_bfloat162 t = __halves2bfloat162(a, b);
    return *reinterpret_cast<uint32_t*>(&t);
}
__device__ __forceinline__ void mma16816(float* c, const uint32_t* a, const uint32_t* b) {
    asm volatile(
        "mma.sync.aligned.m16n8k16.row.col.f32.bf16.bf16.f32 "
        "{%0,%1,%2,%3}, {%4,%5,%6,%7}, {%8,%9}, {%0,%1,%2,%3};\n"
        : "+f"(c[0]), "+f"(c[1]), "+f"(c[2]), "+f"(c[3])
        : "r"(a[0]), "r"(a[1]), "r"(a[2]), "r"(a[3]), "r"(b[0]), "r"(b[1]));
}
__device__ __forceinline__ void ldsm_x4(uint32_t* r, uint32_t saddr) {
    asm volatile("ldmatrix.sync.aligned.m8n8.x4.shared.b16 {%0,%1,%2,%3}, [%4];\n"
        : "=r"(r[0]), "=r"(r[1]), "=r"(r[2]), "=r"(r[3]) : "r"(saddr));
}
__device__ __forceinline__ void cpasync16(uint32_t s, const void* g) {
    asm volatile("cp.async.cg.shared.global [%0], [%1], 16;\n" :: "r"(s), "l"(g));
}
#define CP_COMMIT() asm volatile("cp.async.commit_group;\n")
#define CP_WAIT1()  asm volatile("cp.async.wait_group 1;\n")

// release/acquire flag protocol (replaces fence.sc.gpu pairs)
__device__ __forceinline__ void flag_release_add(int* p) {
    asm volatile("red.release.gpu.global.add.s32 [%0], %1;" :: "l"(p), "r"(1) : "memory");
}
__device__ __forceinline__ int flag_acquire_ld(const int* p) {
    int v;
    asm volatile("ld.acquire.gpu.global.s32 %0, [%1];" : "=r"(v) : "l"(p) : "memory");
    return v;
}

// =====================================================================
// Converters
// =====================================================================
__global__ __launch_bounds__(256)
void convert_x_kernel(const float* __restrict__ X)
{
    if (blockIdx.x == 0) {
        if (threadIdx.x < 256) { g_flags[threadIdx.x] = 0; g_flags[threadIdx.x + 256] = 0; }
    }
    size_t idx = (size_t)blockIdx.x * 256 + threadIdx.x;
    float4 v = ((const float4*)X)[idx];
    __nv_bfloat16 h0,h1,h2,h3,l0,l1,l2,l3;
    split_f(v.x,h0,l0); split_f(v.y,h1,l1); split_f(v.z,h2,l2); split_f(v.w,h3,l3);
    ((uint2*)g_Xhi)[idx] = make_uint2(pack2(h0,h1), pack2(h2,h3));
    ((uint2*)g_Xlo)[idx] = make_uint2(pack2(l0,l1), pack2(l2,l3));
}

__global__ __launch_bounds__(256)
void convert_w_kernel(const float* __restrict__ W)   // [k][n] -> [n][k] bf16 hi/lo
{
    __shared__ float st[32][33];
    const int n0 = blockIdx.x * 32;
    const int k0 = blockIdx.y * 32;
    const int tid = threadIdx.x;
    #pragma unroll
    for (int i = 0; i < 4; i++) {
        int id = tid + 256 * i;
        int kr = id >> 5, nc = id & 31;
        st[kr][nc] = W[(size_t)(k0 + kr) * GATES + n0 + nc];
    }
    __syncthreads();
    #pragma unroll
    for (int i = 0; i < 2; i++) {
        int id = tid + 256 * i;
        int nr = id >> 4, kc = id & 15;
        float v0 = st[2 * kc][nr], v1 = st[2 * kc + 1][nr];
        __nv_bfloat16 h0,h1,l0,l1;
        split_f(v0,h0,l0); split_f(v1,h1,l1);
        size_t o = (size_t)(n0 + nr) * (IN_DIM / 2) + (k0 >> 1) + kc;
        ((uint32_t*)g_Wthi)[o] = pack2(h0,h1);
        ((uint32_t*)g_Wtlo)[o] = pack2(l0,l1);
    }
}

// =====================================================================
// Phase A: g_xw = x @ W_x + b  (unchanged from round 3)
// =====================================================================
#define STG_BYTES 61440
#define OFF_ALO   10240
#define OFF_BHI   20480
#define OFF_BLO   40960
#define PITCH     40

__global__ __launch_bounds__(256, 1)
void xw_gemm_kernel(const float* __restrict__ bias)
{
    extern __shared__ char sm[];
    const uint32_t smu = (uint32_t)__cvta_generic_to_shared(sm);

    const int tid  = threadIdx.x;
    const int lane = tid & 31;
    const int warp = tid >> 5;
    const int g    = lane >> 2;
    const int tg   = lane & 3;
    const int wm   = (warp & 3) * 32;
    const int wn   = (warp >> 2) * 128;
    const size_t m0 = (size_t)blockIdx.y * 128;
    const int    n0 = blockIdx.x * 256;

    const int rA = (lane & 7) | (((lane >> 3) & 1) << 3);
    const int cA = (lane >> 4) * 8;

    float acc[2][16][4];
    #pragma unroll
    for (int a = 0; a < 2; a++)
        #pragma unroll
        for (int b2 = 0; b2 < 16; b2++)
            #pragma unroll
            for (int c = 0; c < 4; c++) acc[a][b2][c] = 0.f;

    auto load_stage = [&](int s, int kk) {
        const int k0 = kk * 32;
        const uint32_t base = smu + s * STG_BYTES;
        #pragma unroll
        for (int i = 0; i < 4; i++) {
            int id  = tid + 256 * i;
            int arr = id >> 9;
            int rc  = id & 511;
            int row = rc >> 2, ch = rc & 3;
            const __nv_bfloat16* src = (arr ? g_Xlo : g_Xhi) + (m0 + row) * (size_t)IN_DIM + k0 + ch * 8;
            cpasync16(base + arr * OFF_ALO + (row * PITCH + ch * 8) * 2, src);
        }
        #pragma unroll
        for (int i = 0; i < 8; i++) {
            int id  = tid + 256 * i;
            int arr = id >> 10;
            int rc  = id & 1023;
            int row = rc >> 2, ch = rc & 3;
            const __nv_bfloat16* src = (arr ? g_Wtlo : g_Wthi) + (size_t)(n0 + row) * IN_DIM + k0 + ch * 8;
            cpasync16(base + OFF_BHI + arr * (OFF_BLO - OFF_BHI) + (row * PITCH + ch * 8) * 2, src);
        }
        CP_COMMIT();
    };

    load_stage(0, 0);
    load_stage(1, 1);

    for (int it = 0; it < 32; ++it) {
        CP_WAIT1();
        __syncthreads();
        if (it + 2 < 32) load_stage((it + 2) % 3, it + 2);
        else CP_COMMIT();

        const uint32_t sb = smu + (it % 3) * STG_BYTES;

        #pragma unroll
        for (int ks = 0; ks < 2; ks++) {
            uint32_t ah[2][4], al[2][4];
            #pragma unroll
            for (int mt = 0; mt < 2; mt++) {
                uint32_t ao = ((wm + mt * 16 + rA) * PITCH + ks * 16 + cA) * 2;
                ldsm_x4(ah[mt], sb + ao);
                ldsm_x4(al[mt], sb + OFF_ALO + ao);
            }
            #pragma unroll
            for (int q = 0; q < 8; q++) {
                uint32_t bh[4], bl[4];
                uint32_t bo = ((wn + q * 16 + rA) * PITCH + ks * 16 + cA) * 2;
                ldsm_x4(bh, sb + OFF_BHI + bo);
                ldsm_x4(bl, sb + OFF_BLO + bo);
                uint32_t b0h[2] = {bh[0], bh[2]}, b0l[2] = {bl[0], bl[2]};
                uint32_t b1h[2] = {bh[1], bh[3]}, b1l[2] = {bl[1], bl[3]};
                #pragma unroll
                for (int mt = 0; mt < 2; mt++) {
                    mma16816(acc[mt][2*q],   ah[mt], b0h);
                    mma16816(acc[mt][2*q],   ah[mt], b0l);
                    mma16816(acc[mt][2*q],   al[mt], b0h);
                    mma16816(acc[mt][2*q+1], ah[mt], b1h);
                    mma16816(acc[mt][2*q+1], ah[mt], b1l);
                    mma16816(acc[mt][2*q+1], al[mt], b1h);
                }
            }
        }
    }

    #pragma unroll
    for (int mt = 0; mt < 2; mt++) {
        #pragma unroll
        for (int nt = 0; nt < 16; nt++) {
            size_t row = m0 + wm + mt * 16 + g;
            int    col = n0 + wn + nt * 8 + 2 * tg;
            float b0 = bias[col], b1 = bias[col + 1];
            float2 v0 = make_float2(acc[mt][nt][0] + b0, acc[mt][nt][1] + b1);
            float2 v1 = make_float2(acc[mt][nt][2] + b0, acc[mt][nt][3] + b1);
            *(float2*)(g_xw + row * GATES + col)       = v0;
            *(float2*)(g_xw + (row + 8) * GATES + col) = v1;
        }
    }
}

// =====================================================================
// Phase B v4: warp = (mt = w&3, k-half = w>>2). Disjoint A reads,
// partial gate sums in 2 gbuf halves, release/acquire sync,
// output stores after release.
// =====================================================================
#define WS_PITCH 1040

__global__ __launch_bounds__(256, 1)
void lstm_rec_kernel(const float* __restrict__ Wh, float* __restrict__ out,
                     int write_tail)
{
    extern __shared__ char smraw[];
    uint32_t* Wsf = (uint32_t*)smraw;                 // 32*1040 u32
    float*    gb  = (float*)(Wsf + 32 * WS_PITCH);    // 2 * [64][33]

    const int tid  = threadIdx.x;
    const int lane = tid & 31;
    const int warp = tid >> 5;
    const int g    = lane >> 2;
    const int tg   = lane & 3;
    const int mt   = warp & 3;        // m-tile 16 rows
    const int kh   = warp >> 2;       // k-half: kt in [kh*32, kh*32+32)
    const int wm   = mt * 16;
    const int j0   = blockIdx.x * 8;

    // one-time: W_h slice -> SMEM fragment layout
    for (int i = tid; i < 32 * 1024; i += 256) {
        int c = i & 31;
        int k = i >> 5;
        int col = (c >> 3) * HID + j0 + (c & 7);
        float v = Wh[(size_t)k * GATES + col];
        __nv_bfloat16 hi, lo; split_f(v, hi, lo);
        int kt = k >> 4, t4 = (k >> 1) & 3, w = (k >> 3) & 1, hf = k & 1;
        int word = c * WS_PITCH + kt * 16 + t4 * 4 + w;
        ((__nv_bfloat16*)Wsf)[word * 2 + hf]       = hi;
        ((__nv_bfloat16*)Wsf)[(word + 2) * 2 + hf] = lo;
    }
    __syncthreads();

    float creg[2] = {0.f, 0.f};

    for (int t = 0; t < T_STEPS; t++) {
        // prefetch xw slice (before the spin)
        float xg[2][4];
        #pragma unroll
        for (int rr = 0; rr < 2; rr++) {
            int p  = tid + 256 * rr;
            int bb = p >> 3, j = p & 7;
            const float* xr = g_xw + (size_t)t * BATCH * GATES + (size_t)bb * GATES + j0 + j;
            xg[rr][0] = xr[0];
            xg[rr][1] = xr[HID];
            xg[rr][2] = xr[2 * HID];
            xg[rr][3] = xr[3 * HID];
        }

        if (t > 0) {
            if (tid == 0) {
                while (flag_acquire_ld(g_flags + (t - 1)) != NCTA) { }
            }
            __syncthreads();

            const uint32_t* ab = g_hfrag + (size_t)(t - 1) * 65536
                                 + (size_t)(kh * 32) * 1024 + mt * 256 + lane * 8;

            uint4 H[4], L[4];
            #pragma unroll
            for (int q = 0; q < 4; q++) {
                H[q] = *(const uint4*)(ab + q * 1024);
                L[q] = *(const uint4*)(ab + q * 1024 + 4);
            }

            float acc[4][4];
            #pragma unroll
            for (int n2 = 0; n2 < 4; n2++)
                #pragma unroll
                for (int c2 = 0; c2 < 4; c2++) acc[n2][c2] = 0.f;

            #pragma unroll 4
            for (int kt2 = 0; kt2 < 32; kt2++) {
                int s = kt2 & 3;
                uint32_t ah[4] = {H[s].x, H[s].y, H[s].z, H[s].w};
                uint32_t al[4] = {L[s].x, L[s].y, L[s].z, L[s].w};
                int ktg = kh * 32 + kt2;
                #pragma unroll
                for (int nt = 0; nt < 4; nt++) {
                    int c = nt * 8 + g;
                    uint4 bf = *(const uint4*)(Wsf + c * WS_PITCH + ktg * 16 + tg * 4);
                    uint32_t bh[2] = {bf.x, bf.y};
                    uint32_t bl[2] = {bf.z, bf.w};
                    mma16816(acc[nt], ah, bh);
                    mma16816(acc[nt], ah, bl);
                    mma16816(acc[nt], al, bh);
                }
                if (kt2 + 4 < 32) {
                    H[s] = *(const uint4*)(ab + (kt2 + 4) * 1024);
                    L[s] = *(const uint4*)(ab + (kt2 + 4) * 1024 + 4);
                }
            }

            // partial gate sums -> gbuf half kh
            float* gbk = gb + kh * 2112;
            #pragma unroll
            for (int nt = 0; nt < 4; nt++) {
                int r = wm + g;
                int c = nt * 8 + 2 * tg;
                gbk[r * 33 + c]           = acc[nt][0];
                gbk[r * 33 + c + 1]       = acc[nt][1];
                gbk[(r + 8) * 33 + c]     = acc[nt][2];
                gbk[(r + 8) * 33 + c + 1] = acc[nt][3];
            }
        }
        __syncthreads();

        // ---- activations + fragment publish (output stores deferred) ----
        float hnv[2], cnv[2];
        #pragma unroll
        for (int rr = 0; rr < 2; rr++) {
            int p  = tid + 256 * rr;
            int bb = p >> 3, j = p & 7;
            int jg = j0 + j;
            float g0 = 0.f, g1 = 0.f, g2 = 0.f, g3 = 0.f;
            if (t > 0) {
                g0 = gb[bb * 33 +  0 + j] + gb[2112 + bb * 33 +  0 + j];
                g1 = gb[bb * 33 +  8 + j] + gb[2112 + bb * 33 +  8 + j];
                g2 = gb[bb * 33 + 16 + j] + gb[2112 + bb * 33 + 16 + j];
                g3 = gb[bb * 33 + 24 + j] + gb[2112 + bb * 33 + 24 + j];
            }
            float gi = g0 + xg[rr][0];
            float gf = g1 + xg[rr][1];
            float gg = g2 + xg[rr][2];
            float go = g3 + xg[rr][3];
            float iv = 1.f / (1.f + expf(-gi));
            float fv = 1.f / (1.f + expf(-gf));
            float gv = tanhf(gg);
            float ov = 1.f / (1.f + expf(-go));
            float cn = fv * creg[rr] + iv * gv;
            float hn = ov * tanhf(cn);
            creg[rr] = cn;
            hnv[rr] = hn; cnv[rr] = cn;

            // publish h in A-fragment layout
            __nv_bfloat16 hh, hl; split_f(hn, hh, hl);
            uint32_t mypk = pack2(hh, hl);
            uint32_t pp   = __shfl_xor_sync(0xffffffffu, mypk, 1);
            if ((tid & 1) == 0) {
                uint32_t hi_pair = (mypk & 0xffffu) | (pp << 16);
                uint32_t lo_pair = (mypk >> 16)     | (pp & 0xffff0000u);
                int kt = jg >> 4, kk = jg & 15, mtt = bb >> 4, r = bb & 15;
                int fl = (r & 7) * 4 + ((kk >> 1) & 3);
                int rg = ((kk >> 3) << 1) | (r >> 3);
                size_t fb = (size_t)t * 65536 + kt * 1024 + mtt * 256 + fl * 8 + rg;
                g_hfrag[fb]     = hi_pair;
                g_hfrag[fb + 4] = lo_pair;
            }
        }

        __syncthreads();
        if (tid == 0) flag_release_add(g_flags + t);

        // off-critical-path output stores
        float* hdst = out + (size_t)t * BATCH * HID;
        #pragma unroll
        for (int rr = 0; rr < 2; rr++) {
            int p  = tid + 256 * rr;
            int bb = p >> 3, j = p & 7;
            int jg = j0 + j;
            hdst[(size_t)bb * HID + jg] = hnv[rr];
            if (t == T_STEPS - 1 && write_tail) {
                size_t base = (size_t)T_STEPS * BATCH * HID;
                out[base + (size_t)bb * HID + jg] = hnv[rr];
                out[base + BATCH * HID + (size_t)bb * HID + jg] = cnv[rr];
            }
        }
    }
}

// =====================================================================
extern "C" void kernel_launch(void* const* d_in, const int* in_sizes, int n_in,
                              void* d_out, int out_size)
{
    const float* x  = (const float*)d_in[0];
    const float* Wx = (const float*)d_in[1];
    const float* Wh = (const float*)d_in[2];
    const float* b  = (const float*)d_in[3];
    float* out = (float*)d_out;

    convert_x_kernel<<<(M_TOT * IN_DIM / 4) / 256, 256>>>(x);
    convert_w_kernel<<<dim3(GATES / 32, IN_DIM / 32), 256>>>(Wx);

    const int smemA = 3 * STG_BYTES;
    cudaFuncSetAttribute(xw_gemm_kernel,
                         cudaFuncAttributeMaxDynamicSharedMemorySize, smemA);
    dim3 gridA(GATES / 256, M_TOT / 128);
    xw_gemm_kernel<<<gridA, 256, smemA>>>(b);

    const int smemB = 32 * WS_PITCH * 4 + 2 * 64 * 33 * 4;
    cudaFuncSetAttribute(lstm_rec_kernel,
                         cudaFuncAttributeMaxDynamicSharedMemorySize, smemB);
    int write_tail = (out_size > T_STEPS * BATCH * HID) ? 1 : 0;
    lstm_rec_kernel<<<NCTA, 256, smemB>>>(Wh, out, write_tail);
}

// round 6
// speedup vs baseline: 3.3242x; 1.2511x over previous
#include <cuda_runtime.h>
#include <cuda_fp16.h>
#include <cstdint>
#include <math.h>

#define T_STEPS 512
#define BATCH   64
#define IN_DIM  1024
#define HID     1024
#define GATES   4096
#define NCTA    128
#define M_TOT   (T_STEPS * BATCH)      // 32768

// ---------------- static scratch ----------------
__device__ __half g_Xh[(size_t)M_TOT * IN_DIM];            // 64 MB (fp16 x)
__device__ __half g_Wthi[(size_t)GATES * IN_DIM];          // 8 MB  [n][k] fp16 hi
__device__ __half g_Wtlo[(size_t)GATES * IN_DIM];          // 8 MB  [n][k] fp16 lo
__device__ float    g_xw[(size_t)T_STEPS * BATCH * GATES]; // 512 MB
__device__ uint32_t g_hfrag[(size_t)T_STEPS * 32768];      // 64 MB (h fp16, mma A-frag layout)
__device__ int      g_flags[T_STEPS];

// ---------------- helpers ----------------
__device__ __forceinline__ void split_h(float v, __half& hi, __half& lo) {
    hi = __float2half(v);
    lo = __float2half(v - __half2float(hi));
}
__device__ __forceinline__ uint32_t pack2h(__half a, __half b) {
    __half2 t = __halves2half2(a, b);
    return *reinterpret_cast<uint32_t*>(&t);
}
__device__ __forceinline__ void mma16816h(float* c, const uint32_t* a, const uint32_t* b) {
    asm volatile(
        "mma.sync.aligned.m16n8k16.row.col.f32.f16.f16.f32 "
        "{%0,%1,%2,%3}, {%4,%5,%6,%7}, {%8,%9}, {%0,%1,%2,%3};\n"
        : "+f"(c[0]), "+f"(c[1]), "+f"(c[2]), "+f"(c[3])
        : "r"(a[0]), "r"(a[1]), "r"(a[2]), "r"(a[3]), "r"(b[0]), "r"(b[1]));
}
__device__ __forceinline__ void ldsm_x4(uint32_t* r, uint32_t saddr) {
    asm volatile("ldmatrix.sync.aligned.m8n8.x4.shared.b16 {%0,%1,%2,%3}, [%4];\n"
        : "=r"(r[0]), "=r"(r[1]), "=r"(r[2]), "=r"(r[3]) : "r"(saddr));
}
__device__ __forceinline__ void cpasync16(uint32_t s, const void* g) {
    asm volatile("cp.async.cg.shared.global [%0], [%1], 16;\n" :: "r"(s), "l"(g));
}
#define CP_COMMIT() asm volatile("cp.async.commit_group;\n")
#define CP_WAIT1()  asm volatile("cp.async.wait_group 1;\n")

__device__ __forceinline__ void flag_release_add(int* p) {
    asm volatile("red.release.gpu.global.add.s32 [%0], %1;" :: "l"(p), "r"(1) : "memory");
}
__device__ __forceinline__ int flag_acquire_ld(const int* p) {
    int v;
    asm volatile("ld.acquire.gpu.global.s32 %0, [%1];" : "=r"(v) : "l"(p) : "memory");
    return v;
}

// =====================================================================
// Converters
// =====================================================================
__global__ __launch_bounds__(256)
void convert_x_kernel(const float* __restrict__ X)
{
    if (blockIdx.x == 0 && threadIdx.x < 256) {
        g_flags[threadIdx.x] = 0; g_flags[threadIdx.x + 256] = 0;
    }
    size_t idx = (size_t)blockIdx.x * 256 + threadIdx.x;   // float4 index
    float4 v = ((const float4*)X)[idx];
    uint2 o;
    o.x = pack2h(__float2half(v.x), __float2half(v.y));
    o.y = pack2h(__float2half(v.z), __float2half(v.w));
    ((uint2*)g_Xh)[idx] = o;
}

__global__ __launch_bounds__(256)
void convert_w_kernel(const float* __restrict__ W)   // [k][n] fp32 -> [n][k] fp16 hi/lo
{
    __shared__ float st[32][33];
    const int n0 = blockIdx.x * 32;
    const int k0 = blockIdx.y * 32;
    const int tid = threadIdx.x;
    #pragma unroll
    for (int i = 0; i < 4; i++) {
        int id = tid + 256 * i;
        int kr = id >> 5, nc = id & 31;
        st[kr][nc] = W[(size_t)(k0 + kr) * GATES + n0 + nc];
    }
    __syncthreads();
    #pragma unroll
    for (int i = 0; i < 2; i++) {
        int id = tid + 256 * i;
        int nr = id >> 4, kc = id & 15;
        float v0 = st[2 * kc][nr], v1 = st[2 * kc + 1][nr];
        __half h0,h1,l0,l1;
        split_h(v0,h0,l0); split_h(v1,h1,l1);
        size_t o = (size_t)(n0 + nr) * (IN_DIM / 2) + (k0 >> 1) + kc;
        ((uint32_t*)g_Wthi)[o] = pack2h(h0,h1);
        ((uint32_t*)g_Wtlo)[o] = pack2h(l0,l1);
    }
}

// =====================================================================
// Phase A: g_xw = x @ W_x + b   (M=32768, N=4096, K=1024)
// CTA 128(M) x 256(N), BK=32, 3-stage cp.async, ldmatrix,
// 2-term fp16: x_f16 @ (Whi + Wlo). 256 threads, warp tile 32m x 128n.
// =====================================================================
#define STG_BYTES 51200
#define OFF_BHI   10240
#define OFF_BLO   30720
#define PITCH     40        // halves per smem row (80 B)

__global__ __launch_bounds__(256, 1)
void xw_gemm_kernel(const float* __restrict__ bias)
{
    extern __shared__ char sm[];
    const uint32_t smu = (uint32_t)__cvta_generic_to_shared(sm);

    const int tid  = threadIdx.x;
    const int lane = tid & 31;
    const int warp = tid >> 5;
    const int g    = lane >> 2;
    const int tg   = lane & 3;
    const int wm   = (warp & 3) * 32;
    const int wn   = (warp >> 2) * 128;
    const size_t m0 = (size_t)blockIdx.y * 128;
    const int    n0 = blockIdx.x * 256;

    const int rA = (lane & 7) | (((lane >> 3) & 1) << 3);
    const int cA = (lane >> 4) * 8;

    float acc[2][16][4];
    #pragma unroll
    for (int a = 0; a < 2; a++)
        #pragma unroll
        for (int b2 = 0; b2 < 16; b2++)
            #pragma unroll
            for (int c = 0; c < 4; c++) acc[a][b2][c] = 0.f;

    auto load_stage = [&](int s, int kk) {
        const int k0 = kk * 32;
        const uint32_t base = smu + s * STG_BYTES;
        // A (x fp16): 128 rows x 4 chunks = 512
        #pragma unroll
        for (int i = 0; i < 2; i++) {
            int id  = tid + 256 * i;            // 0..511
            int row = id >> 2, ch = id & 3;
            const __half* src = g_Xh + (m0 + row) * (size_t)IN_DIM + k0 + ch * 8;
            cpasync16(base + (row * PITCH + ch * 8) * 2, src);
        }
        // B (W hi/lo): 2 arrays x 256 rows x 4 chunks = 2048
        #pragma unroll
        for (int i = 0; i < 8; i++) {
            int id  = tid + 256 * i;            // 0..2047
            int arr = id >> 10;
            int rc  = id & 1023;
            int row = rc >> 2, ch = rc & 3;
            const __half* src = (arr ? g_Wtlo : g_Wthi) + (size_t)(n0 + row) * IN_DIM + k0 + ch * 8;
            cpasync16(base + OFF_BHI + arr * (OFF_BLO - OFF_BHI) + (row * PITCH + ch * 8) * 2, src);
        }
        CP_COMMIT();
    };

    load_stage(0, 0);
    load_stage(1, 1);

    for (int it = 0; it < 32; ++it) {
        CP_WAIT1();
        __syncthreads();
        if (it + 2 < 32) load_stage((it + 2) % 3, it + 2);
        else CP_COMMIT();

        const uint32_t sb = smu + (it % 3) * STG_BYTES;

        #pragma unroll
        for (int ks = 0; ks < 2; ks++) {
            uint32_t ah[2][4];
            #pragma unroll
            for (int mt = 0; mt < 2; mt++) {
                uint32_t ao = ((wm + mt * 16 + rA) * PITCH + ks * 16 + cA) * 2;
                ldsm_x4(ah[mt], sb + ao);
            }
            #pragma unroll
            for (int q = 0; q < 8; q++) {
                uint32_t bh[4], bl[4];
                uint32_t bo = ((wn + q * 16 + rA) * PITCH + ks * 16 + cA) * 2;
                ldsm_x4(bh, sb + OFF_BHI + bo);
                ldsm_x4(bl, sb + OFF_BLO + bo);
                uint32_t b0h[2] = {bh[0], bh[2]}, b0l[2] = {bl[0], bl[2]};
                uint32_t b1h[2] = {bh[1], bh[3]}, b1l[2] = {bl[1], bl[3]};
                #pragma unroll
                for (int mt = 0; mt < 2; mt++) {
                    mma16816h(acc[mt][2*q],   ah[mt], b0h);
                    mma16816h(acc[mt][2*q],   ah[mt], b0l);
                    mma16816h(acc[mt][2*q+1], ah[mt], b1h);
                    mma16816h(acc[mt][2*q+1], ah[mt], b1l);
                }
            }
        }
    }

    // epilogue
    #pragma unroll
    for (int mt = 0; mt < 2; mt++) {
        #pragma unroll
        for (int nt = 0; nt < 16; nt++) {
            size_t row = m0 + wm + mt * 16 + g;
            int    col = n0 + wn + nt * 8 + 2 * tg;
            float b0 = bias[col], b1 = bias[col + 1];
            float2 v0 = make_float2(acc[mt][nt][0] + b0, acc[mt][nt][1] + b1);
            float2 v1 = make_float2(acc[mt][nt][2] + b0, acc[mt][nt][3] + b1);
            *(float2*)(g_xw + row * GATES + col)       = v0;
            *(float2*)(g_xw + (row + 8) * GATES + col) = v1;
        }
    }
}

// =====================================================================
// Phase B: persistent recurrence. 2-term fp16: h_f16 @ (Whi + Wlo).
// h exchanged as fp16 A-fragments (hi only, 128 KB/step total).
// =====================================================================
#define WS_PITCH 1040

__global__ __launch_bounds__(256, 1)
void lstm_rec_kernel(const float* __restrict__ Wh, float* __restrict__ out,
                     int write_tail)
{
    extern __shared__ char smraw[];
    uint32_t* Wsf = (uint32_t*)smraw;                 // 32*1040 u32
    float*    gb  = (float*)(Wsf + 32 * WS_PITCH);    // 2 * [64][33]

    const int tid  = threadIdx.x;
    const int lane = tid & 31;
    const int warp = tid >> 5;
    const int g    = lane >> 2;
    const int tg   = lane & 3;
    const int mt   = warp & 3;        // m-tile (16 rows)
    const int kh   = warp >> 2;       // k-half
    const int wm   = mt * 16;
    const int j0   = blockIdx.x * 8;

    // one-time: W_h slice -> SMEM fragment layout (fp16 hi at words 0-1, lo at 2-3)
    for (int i = tid; i < 32 * 1024; i += 256) {
        int c = i & 31;
        int k = i >> 5;
        int col = (c >> 3) * HID + j0 + (c & 7);
        float v = Wh[(size_t)k * GATES + col];
        __half hi, lo; split_h(v, hi, lo);
        int kt = k >> 4, t4 = (k >> 1) & 3, w = (k >> 3) & 1, hf = k & 1;
        int word = c * WS_PITCH + kt * 16 + t4 * 4 + w;
        ((__half*)Wsf)[word * 2 + hf]       = hi;
        ((__half*)Wsf)[(word + 2) * 2 + hf] = lo;
    }
    __syncthreads();

    float creg[2] = {0.f, 0.f};

    for (int t = 0; t < T_STEPS; t++) {
        // prefetch xw slice (before the spin)
        float xg[2][4];
        #pragma unroll
        for (int rr = 0; rr < 2; rr++) {
            int p  = tid + 256 * rr;
            int bb = p >> 3, j = p & 7;
            const float* xr = g_xw + (size_t)t * BATCH * GATES + (size_t)bb * GATES + j0 + j;
            xg[rr][0] = xr[0];
            xg[rr][1] = xr[HID];
            xg[rr][2] = xr[2 * HID];
            xg[rr][3] = xr[3 * HID];
        }

        if (t > 0) {
            if (tid == 0) {
                while (flag_acquire_ld(g_flags + (t - 1)) != NCTA) { }
            }
            __syncthreads();

            const uint32_t* ab = g_hfrag + (size_t)(t - 1) * 32768
                                 + (size_t)(kh * 32) * 512 + mt * 128 + lane * 4;

            uint4 H[4];
            #pragma unroll
            for (int q = 0; q < 4; q++) H[q] = *(const uint4*)(ab + q * 512);

            float acc[4][4];
            #pragma unroll
            for (int n2 = 0; n2 < 4; n2++)
                #pragma unroll
                for (int c2 = 0; c2 < 4; c2++) acc[n2][c2] = 0.f;

            #pragma unroll 4
            for (int kt2 = 0; kt2 < 32; kt2++) {
                int s = kt2 & 3;
                uint32_t ah[4] = {H[s].x, H[s].y, H[s].z, H[s].w};
                int ktg = kh * 32 + kt2;
                #pragma unroll
                for (int nt = 0; nt < 4; nt++) {
                    int c = nt * 8 + g;
                    uint4 bf = *(const uint4*)(Wsf + c * WS_PITCH + ktg * 16 + tg * 4);
                    uint32_t bh[2] = {bf.x, bf.y};
                    uint32_t bl[2] = {bf.z, bf.w};
                    mma16816h(acc[nt], ah, bh);
                    mma16816h(acc[nt], ah, bl);
                }
                if (kt2 + 4 < 32) H[s] = *(const uint4*)(ab + (kt2 + 4) * 512);
            }

            float* gbk = gb + kh * 2112;
            #pragma unroll
            for (int nt = 0; nt < 4; nt++) {
                int r = wm + g;
                int c = nt * 8 + 2 * tg;
                gbk[r * 33 + c]           = acc[nt][0];
                gbk[r * 33 + c + 1]       = acc[nt][1];
                gbk[(r + 8) * 33 + c]     = acc[nt][2];
                gbk[(r + 8) * 33 + c + 1] = acc[nt][3];
            }
        }
        __syncthreads();

        float hnv[2], cnv[2];
        #pragma unroll
        for (int rr = 0; rr < 2; rr++) {
            int p  = tid + 256 * rr;
            int bb = p >> 3, j = p & 7;
            int jg = j0 + j;
            float g0 = 0.f, g1 = 0.f, g2 = 0.f, g3 = 0.f;
            if (t > 0) {
                g0 = gb[bb * 33 +  0 + j] + gb[2112 + bb * 33 +  0 + j];
                g1 = gb[bb * 33 +  8 + j] + gb[2112 + bb * 33 +  8 + j];
                g2 = gb[bb * 33 + 16 + j] + gb[2112 + bb * 33 + 16 + j];
                g3 = gb[bb * 33 + 24 + j] + gb[2112 + bb * 33 + 24 + j];
            }
            float gi = g0 + xg[rr][0];
            float gf = g1 + xg[rr][1];
            float gg = g2 + xg[rr][2];
            float go = g3 + xg[rr][3];
            float iv = 1.f / (1.f + expf(-gi));
            float fv = 1.f / (1.f + expf(-gf));
            float gv = tanhf(gg);
            float ov = 1.f / (1.f + expf(-go));
            float cn = fv * creg[rr] + iv * gv;
            float hn = ov * tanhf(cn);
            creg[rr] = cn;
            hnv[rr] = hn; cnv[rr] = cn;

            // publish h (fp16) in A-fragment layout: one u32 per element pair
            uint32_t mypk = (uint32_t)__half_as_ushort(__float2half(hn));
            uint32_t pp   = __shfl_xor_sync(0xffffffffu, mypk, 1);
            if ((tid & 1) == 0) {
                uint32_t pair = mypk | (pp << 16);
                int kt = jg >> 4, kk = jg & 15, mtt = bb >> 4, r = bb & 15;
                int fl = (r & 7) * 4 + ((kk >> 1) & 3);
                int rg = ((kk >> 3) << 1) | (r >> 3);
                size_t fb = (size_t)t * 32768 + kt * 512 + mtt * 128 + fl * 4 + rg;
                g_hfrag[fb] = pair;
            }
        }

        __syncthreads();
        if (tid == 0) flag_release_add(g_flags + t);

        // off-critical-path output stores
        float* hdst = out + (size_t)t * BATCH * HID;
        #pragma unroll
        for (int rr = 0; rr < 2; rr++) {
            int p  = tid + 256 * rr;
            int bb = p >> 3, j = p & 7;
            int jg = j0 + j;
            hdst[(size_t)bb * HID + jg] = hnv[rr];
            if (t == T_STEPS - 1 && write_tail) {
                size_t base = (size_t)T_STEPS * BATCH * HID;
                out[base + (size_t)bb * HID + jg] = hnv[rr];
                out[base + BATCH * HID + (size_t)bb * HID + jg] = cnv[rr];
            }
        }
    }
}

// =====================================================================
extern "C" void kernel_launch(void* const* d_in, const int* in_sizes, int n_in,
                              void* d_out, int out_size)
{
    const float* x  = (const float*)d_in[0];
    const float* Wx = (const float*)d_in[1];
    const float* Wh = (const float*)d_in[2];
    const float* b  = (const float*)d_in[3];
    float* out = (float*)d_out;

    convert_x_kernel<<<(M_TOT * IN_DIM / 4) / 256, 256>>>(x);
    convert_w_kernel<<<dim3(GATES / 32, IN_DIM / 32), 256>>>(Wx);

    const int smemA = 3 * STG_BYTES;   // 153600
    cudaFuncSetAttribute(xw_gemm_kernel,
                         cudaFuncAttributeMaxDynamicSharedMemorySize, smemA);
    dim3 gridA(GATES / 256, M_TOT / 128);   // 16 x 256
    xw_gemm_kernel<<<gridA, 256, smemA>>>(b);

    const int smemB = 32 * WS_PITCH * 4 + 2 * 64 * 33 * 4;
    cudaFuncSetAttribute(lstm_rec_kernel,
                         cudaFuncAttributeMaxDynamicSharedMemorySize, smemB);
    int write_tail = (out_size > T_STEPS * BATCH * HID) ? 1 : 0;
    lstm_rec_kernel<<<NCTA, 256, smemB>>>(Wh, out, write_tail);
}

// round 7
// speedup vs baseline: 4.1568x; 1.2505x over previous
#include <cuda_runtime.h>
#include <cuda_fp16.h>
#include <cstdint>
#include <math.h>

#define T_STEPS 512
#define BATCH   64
#define IN_DIM  1024
#define HID     1024
#define GATES   4096
#define NCTA    128
#define M_TOT   (T_STEPS * BATCH)      // 32768

// ---------------- static scratch ----------------
__device__ __half g_Xh[(size_t)M_TOT * IN_DIM];            // 64 MB (fp16 x)
__device__ __half g_Wth[(size_t)GATES * IN_DIM];           // 8 MB  [n][k] fp16
__device__ float    g_xw[(size_t)T_STEPS * BATCH * GATES]; // 512 MB
__device__ uint32_t g_hfrag[(size_t)T_STEPS * 32768];      // 64 MB (h fp16, mma A-frag layout)
__device__ int      g_flags[T_STEPS];

// ---------------- helpers ----------------
__device__ __forceinline__ uint32_t pack2h(__half a, __half b) {
    __half2 t = __halves2half2(a, b);
    return *reinterpret_cast<uint32_t*>(&t);
}
__device__ __forceinline__ void mma16816h(float* c, const uint32_t* a, const uint32_t* b) {
    asm volatile(
        "mma.sync.aligned.m16n8k16.row.col.f32.f16.f16.f32 "
        "{%0,%1,%2,%3}, {%4,%5,%6,%7}, {%8,%9}, {%0,%1,%2,%3};\n"
        : "+f"(c[0]), "+f"(c[1]), "+f"(c[2]), "+f"(c[3])
        : "r"(a[0]), "r"(a[1]), "r"(a[2]), "r"(a[3]), "r"(b[0]), "r"(b[1]));
}
__device__ __forceinline__ void ldsm_x4(uint32_t* r, uint32_t saddr) {
    asm volatile("ldmatrix.sync.aligned.m8n8.x4.shared.b16 {%0,%1,%2,%3}, [%4];\n"
        : "=r"(r[0]), "=r"(r[1]), "=r"(r[2]), "=r"(r[3]) : "r"(saddr));
}
__device__ __forceinline__ void cpasync16(uint32_t s, const void* g) {
    asm volatile("cp.async.cg.shared.global [%0], [%1], 16;\n" :: "r"(s), "l"(g));
}
#define CP_COMMIT() asm volatile("cp.async.commit_group;\n")
#define CP_WAIT1()  asm volatile("cp.async.wait_group 1;\n")

__device__ __forceinline__ void flag_release_add(int* p) {
    asm volatile("red.release.gpu.global.add.s32 [%0], %1;" :: "l"(p), "r"(1) : "memory");
}
__device__ __forceinline__ int flag_acquire_ld(const int* p) {
    int v;
    asm volatile("ld.acquire.gpu.global.s32 %0, [%1];" : "=r"(v) : "l"(p) : "memory");
    return v;
}

// =====================================================================
// Converters
// =====================================================================
__global__ __launch_bounds__(256)
void convert_x_kernel(const float* __restrict__ X)
{
    if (blockIdx.x == 0 && threadIdx.x < 256) {
        g_flags[threadIdx.x] = 0; g_flags[threadIdx.x + 256] = 0;
    }
    size_t idx = (size_t)blockIdx.x * 256 + threadIdx.x;   // float4 index
    float4 v = ((const float4*)X)[idx];
    uint2 o;
    o.x = pack2h(__float2half(v.x), __float2half(v.y));
    o.y = pack2h(__float2half(v.z), __float2half(v.w));
    ((uint2*)g_Xh)[idx] = o;
}

__global__ __launch_bounds__(256)
void convert_w_kernel(const float* __restrict__ W)   // [k][n] fp32 -> [n][k] fp16
{
    __shared__ float st[32][33];
    const int n0 = blockIdx.x * 32;
    const int k0 = blockIdx.y * 32;
    const int tid = threadIdx.x;
    #pragma unroll
    for (int i = 0; i < 4; i++) {
        int id = tid + 256 * i;
        int kr = id >> 5, nc = id & 31;
        st[kr][nc] = W[(size_t)(k0 + kr) * GATES + n0 + nc];
    }
    __syncthreads();
    #pragma unroll
    for (int i = 0; i < 2; i++) {
        int id = tid + 256 * i;
        int nr = id >> 4, kc = id & 15;
        float v0 = st[2 * kc][nr], v1 = st[2 * kc + 1][nr];
        size_t o = (size_t)(n0 + nr) * (IN_DIM / 2) + (k0 >> 1) + kc;
        ((uint32_t*)g_Wth)[o] = pack2h(__float2half(v0), __float2half(v1));
    }
}

// =====================================================================
// Phase A: g_xw = x_f16 @ W_f16 + b   (M=32768, N=4096, K=1024)
// CTA 128(M) x 256(N), BK=32, 3-stage cp.async, ldmatrix, single-term fp16.
// =====================================================================
#define STG_BYTES 30720
#define OFF_BHI   10240
#define PITCH     40        // halves per smem row (80 B)

__global__ __launch_bounds__(256, 1)
void xw_gemm_kernel(const float* __restrict__ bias)
{
    extern __shared__ char sm[];
    const uint32_t smu = (uint32_t)__cvta_generic_to_shared(sm);

    const int tid  = threadIdx.x;
    const int lane = tid & 31;
    const int warp = tid >> 5;
    const int g    = lane >> 2;
    const int tg   = lane & 3;
    const int wm   = (warp & 3) * 32;
    const int wn   = (warp >> 2) * 128;
    const size_t m0 = (size_t)blockIdx.y * 128;
    const int    n0 = blockIdx.x * 256;

    const int rA = (lane & 7) | (((lane >> 3) & 1) << 3);
    const int cA = (lane >> 4) * 8;

    float acc[2][16][4];
    #pragma unroll
    for (int a = 0; a < 2; a++)
        #pragma unroll
        for (int b2 = 0; b2 < 16; b2++)
            #pragma unroll
            for (int c = 0; c < 4; c++) acc[a][b2][c] = 0.f;

    auto load_stage = [&](int s, int kk) {
        const int k0 = kk * 32;
        const uint32_t base = smu + s * STG_BYTES;
        // A (x fp16): 128 rows x 4 chunks = 512
        #pragma unroll
        for (int i = 0; i < 2; i++) {
            int id  = tid + 256 * i;            // 0..511
            int row = id >> 2, ch = id & 3;
            const __half* src = g_Xh + (m0 + row) * (size_t)IN_DIM + k0 + ch * 8;
            cpasync16(base + (row * PITCH + ch * 8) * 2, src);
        }
        // B (W fp16): 256 rows x 4 chunks = 1024
        #pragma unroll
        for (int i = 0; i < 4; i++) {
            int id  = tid + 256 * i;            // 0..1023
            int row = id >> 2, ch = id & 3;
            const __half* src = g_Wth + (size_t)(n0 + row) * IN_DIM + k0 + ch * 8;
            cpasync16(base + OFF_BHI + (row * PITCH + ch * 8) * 2, src);
        }
        CP_COMMIT();
    };

    load_stage(0, 0);
    load_stage(1, 1);

    for (int it = 0; it < 32; ++it) {
        CP_WAIT1();
        __syncthreads();
        if (it + 2 < 32) load_stage((it + 2) % 3, it + 2);
        else CP_COMMIT();

        const uint32_t sb = smu + (it % 3) * STG_BYTES;

        #pragma unroll
        for (int ks = 0; ks < 2; ks++) {
            uint32_t ah[2][4];
            #pragma unroll
            for (int mt = 0; mt < 2; mt++) {
                uint32_t ao = ((wm + mt * 16 + rA) * PITCH + ks * 16 + cA) * 2;
                ldsm_x4(ah[mt], sb + ao);
            }
            #pragma unroll
            for (int q = 0; q < 8; q++) {
                uint32_t bh[4];
                uint32_t bo = ((wn + q * 16 + rA) * PITCH + ks * 16 + cA) * 2;
                ldsm_x4(bh, sb + OFF_BHI + bo);
                uint32_t b0h[2] = {bh[0], bh[2]};
                uint32_t b1h[2] = {bh[1], bh[3]};
                #pragma unroll
                for (int mt = 0; mt < 2; mt++) {
                    mma16816h(acc[mt][2*q],   ah[mt], b0h);
                    mma16816h(acc[mt][2*q+1], ah[mt], b1h);
                }
            }
        }
    }

    // epilogue
    #pragma unroll
    for (int mt = 0; mt < 2; mt++) {
        #pragma unroll
        for (int nt = 0; nt < 16; nt++) {
            size_t row = m0 + wm + mt * 16 + g;
            int    col = n0 + wn + nt * 8 + 2 * tg;
            float b0 = bias[col], b1 = bias[col + 1];
            float2 v0 = make_float2(acc[mt][nt][0] + b0, acc[mt][nt][1] + b1);
            float2 v1 = make_float2(acc[mt][nt][2] + b0, acc[mt][nt][3] + b1);
            *(float2*)(g_xw + row * GATES + col)       = v0;
            *(float2*)(g_xw + (row + 8) * GATES + col) = v1;
        }
    }
}

// =====================================================================
// Phase B: persistent recurrence, single-term fp16: h_f16 @ W_f16.
// =====================================================================
#define WS_PITCH 520      // u32 per W column (fp16 hi only; 520 % 32 == 8)

__global__ __launch_bounds__(256, 1)
void lstm_rec_kernel(const float* __restrict__ Wh, float* __restrict__ out,
                     int write_tail)
{
    extern __shared__ char smraw[];
    uint32_t* Wsf = (uint32_t*)smraw;                 // 32*520 u32 = 66560 B
    float*    gb  = (float*)(Wsf + 32 * WS_PITCH);    // 2 * [64][33]

    const int tid  = threadIdx.x;
    const int lane = tid & 31;
    const int warp = tid >> 5;
    const int g    = lane >> 2;
    const int tg   = lane & 3;
    const int mt   = warp & 3;        // m-tile (16 rows)
    const int kh   = warp >> 2;       // k-half
    const int wm   = mt * 16;
    const int j0   = blockIdx.x * 8;

    // one-time: W_h slice -> SMEM fragment layout (fp16, 2 words per frag)
    for (int i = tid; i < 32 * 1024; i += 256) {
        int c = i & 31;
        int k = i >> 5;
        int col = (c >> 3) * HID + j0 + (c & 7);
        float v = Wh[(size_t)k * GATES + col];
        int kt = k >> 4, t4 = (k >> 1) & 3, w = (k >> 3) & 1, hf = k & 1;
        int word = c * WS_PITCH + kt * 8 + t4 * 2 + w;
        ((__half*)Wsf)[word * 2 + hf] = __float2half(v);
    }
    __syncthreads();

    float creg[2] = {0.f, 0.f};

    for (int t = 0; t < T_STEPS; t++) {
        // prefetch xw slice (before the spin)
        float xg[2][4];
        #pragma unroll
        for (int rr = 0; rr < 2; rr++) {
            int p  = tid + 256 * rr;
            int bb = p >> 3, j = p & 7;
            const float* xr = g_xw + (size_t)t * BATCH * GATES + (size_t)bb * GATES + j0 + j;
            xg[rr][0] = xr[0];
            xg[rr][1] = xr[HID];
            xg[rr][2] = xr[2 * HID];
            xg[rr][3] = xr[3 * HID];
        }

        if (t > 0) {
            if (tid == 0) {
                while (flag_acquire_ld(g_flags + (t - 1)) != NCTA) { }
            }
            __syncthreads();

            const uint32_t* ab = g_hfrag + (size_t)(t - 1) * 32768
                                 + (size_t)(kh * 32) * 512 + mt * 128 + lane * 4;

            uint4 H[4];
            #pragma unroll
            for (int q = 0; q < 4; q++) H[q] = *(const uint4*)(ab + q * 512);

            float acc[4][4];
            #pragma unroll
            for (int n2 = 0; n2 < 4; n2++)
                #pragma unroll
                for (int c2 = 0; c2 < 4; c2++) acc[n2][c2] = 0.f;

            #pragma unroll 4
            for (int kt2 = 0; kt2 < 32; kt2++) {
                int s = kt2 & 3;
                uint32_t ah[4] = {H[s].x, H[s].y, H[s].z, H[s].w};
                int ktg = kh * 32 + kt2;
                #pragma unroll
                for (int nt = 0; nt < 4; nt++) {
                    int c = nt * 8 + g;
                    uint2 bf = *(const uint2*)(Wsf + c * WS_PITCH + ktg * 8 + tg * 2);
                    uint32_t bh[2] = {bf.x, bf.y};
                    mma16816h(acc[nt], ah, bh);
                }
                if (kt2 + 4 < 32) H[s] = *(const uint4*)(ab + (kt2 + 4) * 512);
            }

            float* gbk = gb + kh * 2112;
            #pragma unroll
            for (int nt = 0; nt < 4; nt++) {
                int r = wm + g;
                int c = nt * 8 + 2 * tg;
                gbk[r * 33 + c]           = acc[nt][0];
                gbk[r * 33 + c + 1]       = acc[nt][1];
                gbk[(r + 8) * 33 + c]     = acc[nt][2];
                gbk[(r + 8) * 33 + c + 1] = acc[nt][3];
            }
        }
        __syncthreads();

        float hnv[2], cnv[2];
        #pragma unroll
        for (int rr = 0; rr < 2; rr++) {
            int p  = tid + 256 * rr;
            int bb = p >> 3, j = p & 7;
            int jg = j0 + j;
            float g0 = 0.f, g1 = 0.f, g2 = 0.f, g3 = 0.f;
            if (t > 0) {
                g0 = gb[bb * 33 +  0 + j] + gb[2112 + bb * 33 +  0 + j];
                g1 = gb[bb * 33 +  8 + j] + gb[2112 + bb * 33 +  8 + j];
                g2 = gb[bb * 33 + 16 + j] + gb[2112 + bb * 33 + 16 + j];
                g3 = gb[bb * 33 + 24 + j] + gb[2112 + bb * 33 + 24 + j];
            }
            float gi = g0 + xg[rr][0];
            float gf = g1 + xg[rr][1];
            float gg = g2 + xg[rr][2];
            float go = g3 + xg[rr][3];
            float iv = 1.f / (1.f + expf(-gi));
            float fv = 1.f / (1.f + expf(-gf));
            float gv = tanhf(gg);
            float ov = 1.f / (1.f + expf(-go));
            float cn = fv * creg[rr] + iv * gv;
            float hn = ov * tanhf(cn);
            creg[rr] = cn;
            hnv[rr] = hn; cnv[rr] = cn;

            // publish h (fp16) in A-fragment layout: one u32 per element pair
            uint32_t mypk = (uint32_t)__half_as_ushort(__float2half(hn));
            uint32_t pp   = __shfl_xor_sync(0xffffffffu, mypk, 1);
            if ((tid & 1) == 0) {
                uint32_t pair = mypk | (pp << 16);
                int kt = jg >> 4, kk = jg & 15, mtt = bb >> 4, r = bb & 15;
                int fl = (r & 7) * 4 + ((kk >> 1) & 3);
                int rg = ((kk >> 3) << 1) | (r >> 3);
                size_t fb = (size_t)t * 32768 + kt * 512 + mtt * 128 + fl * 4 + rg;
                g_hfrag[fb] = pair;
            }
        }

        __syncthreads();
        if (tid == 0) flag_release_add(g_flags + t);

        // off-critical-path output stores
        float* hdst = out + (size_t)t * BATCH * HID;
        #pragma unroll
        for (int rr = 0; rr < 2; rr++) {
            int p  = tid + 256 * rr;
            int bb = p >> 3, j = p & 7;
            int jg = j0 + j;
            hdst[(size_t)bb * HID + jg] = hnv[rr];
            if (t == T_STEPS - 1 && write_tail) {
                size_t base = (size_t)T_STEPS * BATCH * HID;
                out[base + (size_t)bb * HID + jg] = hnv[rr];
                out[base + BATCH * HID + (size_t)bb * HID + jg] = cnv[rr];
            }
        }
    }
}

// =====================================================================
extern "C" void kernel_launch(void* const* d_in, const int* in_sizes, int n_in,
                              void* d_out, int out_size)
{
    const float* x  = (const float*)d_in[0];
    const float* Wx = (const float*)d_in[1];
    const float* Wh = (const float*)d_in[2];
    const float* b  = (const float*)d_in[3];
    float* out = (float*)d_out;

    convert_x_kernel<<<(M_TOT * IN_DIM / 4) / 256, 256>>>(x);
    convert_w_kernel<<<dim3(GATES / 32, IN_DIM / 32), 256>>>(Wx);

    const int smemA = 3 * STG_BYTES;   // 92160
    cudaFuncSetAttribute(xw_gemm_kernel,
                         cudaFuncAttributeMaxDynamicSharedMemorySize, smemA);
    dim3 gridA(GATES / 256, M_TOT / 128);   // 16 x 256
    xw_gemm_kernel<<<gridA, 256, smemA>>>(b);

    const int smemB = 32 * WS_PITCH * 4 + 2 * 64 * 33 * 4;   // 66560 + 8448
    cudaFuncSetAttribute(lstm_rec_kernel,
                         cudaFuncAttributeMaxDynamicSharedMemorySize, smemB);
    int write_tail = (out_size > T_STEPS * BATCH * HID) ? 1 : 0;
    lstm_rec_kernel<<<NCTA, 256, smemB>>>(Wh, out, write_tail);
}